// round 10
// baseline (speedup 1.0000x reference)
#include <cuda_runtime.h>
#include <cuda_bf16.h>
#include <math.h>
#include <stdint.h>

#define NFFT  16000
#define DIN   2048
#define BATCH 1024
#define OUTN  3000
#define OUTP  3072
#define TPB   512

// ---------------- device globals (no runtime allocation) ----------------
__device__ float2 g_tw[NFFT];                          // W_16000^t = (cos, -sin)
__device__ __nv_bfloat16 g_zhi[BATCH * (size_t)NFFT];
__device__ __nv_bfloat16 g_zlo[BATCH * (size_t)NFFT];
__device__ __nv_bfloat16 g_whi[OUTP * (size_t)NFFT];
__device__ __nv_bfloat16 g_wlo[OUTP * (size_t)NFFT];

// ---------------- helpers ----------------
__device__ __forceinline__ uint32_t smem_u32(const void* p) {
    uint32_t a;
    asm("{ .reg .u64 t; cvta.to.shared.u64 t, %1; cvt.u32.u64 %0, t; }" : "=r"(a) : "l"(p));
    return a;
}
__device__ __forceinline__ int rev7(int x) { return (int)(__brev((unsigned)x) >> 25); }
__device__ __forceinline__ int rev5(int n) {
    int d0 = n % 5; n /= 5; int d1 = n % 5; int d2 = n / 5;
    return d0 * 25 + d1 * 5 + d2;
}
__device__ __forceinline__ float2 cmul(float2 a, float2 b) {
    return make_float2(a.x * b.x - a.y * b.y, a.x * b.y + a.y * b.x);
}

// ---------------- portable tensor-core / async-copy PTX (sm_80+) ----------------
#define CP_ASYNC16(dst, src) \
    asm volatile("cp.async.cg.shared.global [%0], [%1], 16;" :: "r"(dst), "l"(src))
#define CP_COMMIT() asm volatile("cp.async.commit_group;" ::: "memory")
#define CP_WAIT1()  asm volatile("cp.async.wait_group 1;" ::: "memory")

__device__ __forceinline__ void ldmx4(uint32_t* r, uint32_t addr) {
    asm volatile("ldmatrix.sync.aligned.m8n8.x4.shared.b16 {%0,%1,%2,%3}, [%4];"
        : "=r"(r[0]), "=r"(r[1]), "=r"(r[2]), "=r"(r[3]) : "r"(addr));
}
__device__ __forceinline__ void mma_bf16(float* d, const uint32_t* a, const uint32_t* b) {
    asm volatile(
        "mma.sync.aligned.m16n8k16.row.col.f32.bf16.bf16.f32 "
        "{%0,%1,%2,%3}, {%4,%5,%6,%7}, {%8,%9}, {%0,%1,%2,%3};"
        : "+f"(d[0]), "+f"(d[1]), "+f"(d[2]), "+f"(d[3])
        : "r"(a[0]), "r"(a[1]), "r"(a[2]), "r"(a[3]), "r"(b[0]), "r"(b[1]));
}

// ---------------------------------------------------------------------------
// twiddle table init: g_tw[t] = exp(-2 pi i t / 16000)
// ---------------------------------------------------------------------------
__global__ void twinit_kernel() {
    int t = blockIdx.x * blockDim.x + threadIdx.x;
    if (t < NFFT) {
        double s, c;
        sincospi(-(double)t / 8000.0, &s, &c);
        g_tw[t] = make_float2((float)c, (float)s);
    }
}

// ---------------------------------------------------------------------------
// W -> bf16 hi/lo split, padded to OUTP rows (pad rows = 0)
// ---------------------------------------------------------------------------
__global__ void wconv_kernel(const float* __restrict__ W) {
    int row = blockIdx.x;
    const float4* src = (const float4*)(W + (size_t)row * NFFT);
    uint2* dhi = (uint2*)(g_whi + (size_t)row * NFFT);
    uint2* dlo = (uint2*)(g_wlo + (size_t)row * NFFT);
    bool ok = row < OUTN;
    for (int c4 = threadIdx.x; c4 < NFFT / 4; c4 += blockDim.x) {
        float4 v = ok ? __ldg(src + c4) : make_float4(0.f, 0.f, 0.f, 0.f);
        float vv[4] = {v.x, v.y, v.z, v.w};
        unsigned short h[4], l[4];
#pragma unroll
        for (int i = 0; i < 4; i++) {
            __nv_bfloat16 hb = __float2bfloat16(vv[i]);
            __nv_bfloat16 lb = __float2bfloat16(vv[i] - __bfloat162float(hb));
            h[i] = __bfloat16_as_ushort(hb);
            l[i] = __bfloat16_as_ushort(lb);
        }
        uint2 hp, lp;
        hp.x = (uint32_t)h[0] | ((uint32_t)h[1] << 16);
        hp.y = (uint32_t)h[2] | ((uint32_t)h[3] << 16);
        lp.x = (uint32_t)l[0] | ((uint32_t)l[1] << 16);
        lp.y = (uint32_t)l[2] | ((uint32_t)l[3] << 16);
        dhi[c4] = hp;
        dlo[c4] = lp;
    }
}

// ---------------------------------------------------------------------------
// Fused count-sketch + forward FFT(p0 + i p1) + pointwise product + inverse FFT
// (table-driven twiddles). One block per batch row. Output: z as bf16 hi/lo.
// ---------------------------------------------------------------------------
__global__ void __launch_bounds__(TPB, 1) fftconv_kernel(
    const float* __restrict__ x0, const float* __restrict__ x1,
    const int* __restrict__ h0, const int* __restrict__ h1,
    const int* __restrict__ s0, const int* __restrict__ s1)
{
    extern __shared__ float2 sh[];  // 16000 complex = 128000 B
    const int b = blockIdx.x, tid = threadIdx.x;

    for (int i = tid; i < NFFT; i += TPB) sh[i] = make_float2(0.f, 0.f);
    __syncthreads();

    for (int i = tid; i < DIN; i += TPB) {
        int bin = h0[i];
        float v = x0[b * DIN + i] * (float)(2 * s0[i] - 1);
        int addr = rev5(bin % 125) + 125 * rev7(bin / 125);
        atomicAdd(&sh[addr].x, v);
        bin = h1[i];
        v = x1[b * DIN + i] * (float)(2 * s1[i] - 1);
        addr = rev5(bin % 125) + 125 * rev7(bin / 125);
        atomicAdd(&sh[addr].y, v);
    }
    __syncthreads();

    // forward radix-2 DIT over n2 (stride 125)
    for (int len = 2; len <= 128; len <<= 1) {
        int half = len >> 1, step = NFFT / len;
        for (int t = tid; t < 8000; t += TPB) {
            int col = t % 125, bf = t / 125;
            int g = bf / half, pos = bf - g * half;
            int ia = col + 125 * (g * len + pos);
            int ib = ia + 125 * half;
            float2 w = __ldg(&g_tw[pos * step]);
            float2 A = sh[ia], B = sh[ib];
            float tr = B.x * w.x - B.y * w.y;
            float ti = B.x * w.y + B.y * w.x;
            sh[ia] = make_float2(A.x + tr, A.y + ti);
            sh[ib] = make_float2(A.x - tr, A.y - ti);
        }
        __syncthreads();
    }

    // forward mid twiddle W_N^{n1*k2}
    for (int idx = tid; idx < NFFT; idx += TPB) {
        int n1 = rev5(idx % 125), k2 = idx / 125;
        float2 w = __ldg(&g_tw[n1 * k2]);
        sh[idx] = cmul(sh[idx], w);
    }
    __syncthreads();

    const float W5c[5]  = {1.f, 0.30901699f, -0.80901699f, -0.80901699f, 0.30901699f};
    const float W5sF[5] = {0.f, -0.95105652f, -0.58778525f, 0.58778525f, 0.95105652f};
    const float W5sI[5] = {0.f,  0.95105652f,  0.58778525f, -0.58778525f, -0.95105652f};

    // forward radix-5 DIT over n1 (stride 1)
    for (int len = 5; len <= 125; len *= 5) {
        int span = len / 5, step = NFFT / len;
        for (int t = tid; t < 3200; t += TPB) {
            int k2 = t & 127, bf = t >> 7;
            int g = bf / span, pos = bf - g * span;
            int base = 125 * k2 + g * len + pos;
            float2 a[5];
#pragma unroll
            for (int q = 0; q < 5; q++) a[q] = sh[base + q * span];
#pragma unroll
            for (int t5 = 1; t5 < 5; t5++) {
                float2 w = __ldg(&g_tw[pos * t5 * step]);
                a[t5] = cmul(a[t5], w);
            }
#pragma unroll
            for (int q = 0; q < 5; q++) {
                float2 o = a[0];
#pragma unroll
                for (int t5 = 1; t5 < 5; t5++) {
                    int r = (q * t5) % 5;
                    o.x += a[t5].x * W5c[r] - a[t5].y * W5sF[r];
                    o.y += a[t5].x * W5sF[r] + a[t5].y * W5c[r];
                }
                sh[base + q * span] = o;
            }
        }
        __syncthreads();
    }

    // pointwise: separate P0/P1, Z = P0*P1, Hermitian fill
    for (int k = tid; k <= 8000; k += TPB) {
        int kc = (k == 0) ? 0 : (NFFT - k);
        int sA = (k >> 7) + 125 * (k & 127);
        int sB = (kc >> 7) + 125 * (kc & 127);
        float2 FA = sh[sA], FB = sh[sB];
        float p0r = 0.5f * (FA.x + FB.x), p0i = 0.5f * (FA.y - FB.y);
        float p1r = 0.5f * (FA.y + FB.y), p1i = 0.5f * (FB.x - FA.x);
        float zr = p0r * p1r - p0i * p1i;
        float zi = p0r * p1i + p0i * p1r;
        sh[sA] = make_float2(zr, zi);
        if (sB != sA) sh[sB] = make_float2(zr, -zi);
    }
    __syncthreads();

    // inverse radix-5 DIF over k1 (stride 1)
    for (int len = 125; len >= 5; len /= 5) {
        int span = len / 5, step = NFFT / len;
        for (int t = tid; t < 3200; t += TPB) {
            int k2 = t & 127, bf = t >> 7;
            int g = bf / span, pos = bf - g * span;
            int base = 125 * k2 + g * len + pos;
            float2 a[5];
#pragma unroll
            for (int q = 0; q < 5; q++) a[q] = sh[base + q * span];
#pragma unroll
            for (int q = 0; q < 5; q++) {
                float2 o = a[0];
#pragma unroll
                for (int t5 = 1; t5 < 5; t5++) {
                    int r = (q * t5) % 5;
                    o.x += a[t5].x * W5c[r] - a[t5].y * W5sI[r];
                    o.y += a[t5].x * W5sI[r] + a[t5].y * W5c[r];
                }
                float2 w = __ldg(&g_tw[pos * q * step]);
                w.y = -w.y;
                sh[base + q * span] = cmul(o, w);
            }
        }
        __syncthreads();
    }

    // inverse mid twiddle (conjugate)
    for (int idx = tid; idx < NFFT; idx += TPB) {
        int n1 = rev5(idx % 125), k2 = idx / 125;
        float2 w = __ldg(&g_tw[n1 * k2]);
        w.y = -w.y;
        sh[idx] = cmul(sh[idx], w);
    }
    __syncthreads();

    // inverse radix-2 DIF over k2 (stride 125)
    for (int len = 128; len >= 2; len >>= 1) {
        int half = len >> 1, step = NFFT / len;
        for (int t = tid; t < 8000; t += TPB) {
            int col = t % 125, bf = t / 125;
            int g = bf / half, pos = bf - g * half;
            int ia = col + 125 * (g * len + pos);
            int ib = ia + 125 * half;
            float2 A = sh[ia], B = sh[ib];
            float2 sum = make_float2(A.x + B.x, A.y + B.y);
            float2 dif = make_float2(A.x - B.x, A.y - B.y);
            float2 w = __ldg(&g_tw[pos * step]);
            w.y = -w.y;
            sh[ia] = sum;
            sh[ib] = cmul(dif, w);
        }
        __syncthreads();
    }

    // store z as bf16 hi/lo, unpermute, scale 1/N
    for (int n = tid; n < NFFT; n += TPB) {
        int addr = rev5(n % 125) + 125 * rev7(n / 125);
        float zr = sh[addr].x * (1.f / 16000.f);
        __nv_bfloat16 hb = __float2bfloat16(zr);
        g_zhi[b * (size_t)NFFT + n] = hb;
        g_zlo[b * (size_t)NFFT + n] = __float2bfloat16(zr - __bfloat162float(hb));
    }
}

// ---------------------------------------------------------------------------
// GEMM via mma.sync (HMMA, portable PTX): out = relu(z @ W^T + b)
// bf16 split precision, 3 passes (hi*hi + lo*hi + hi*lo), fp32 accumulate.
// CTA tile 128x192, K-chunk 64, cp.async double buffering. Grid 16x8 = 128
// CTAs = one uniform wave on 148 SMs.
// ---------------------------------------------------------------------------
#define GBM 128
#define GBN 192
#define GBK 64
#define GT  256
#define LDA 144                       // smem row pitch bytes (64 bf16 + 8 pad)
#define A_TILE (GBM * LDA)            // 18432
#define B_TILE (GBN * LDA)            // 27648
#define OFF_ALO  A_TILE
#define OFF_BHI  (2 * A_TILE)
#define OFF_BLO  (2 * A_TILE + B_TILE)
#define ST_STRIDE (2 * A_TILE + 2 * B_TILE)   // 92160
#define GSMEM_TOTAL (2 * ST_STRIDE)           // 184320

__device__ __forceinline__ void load_chunk(
    uint32_t sbase, const char* Ah, const char* Al,
    const char* Bh, const char* Bl, int kb, int tid)
{
#pragma unroll
    for (int j = 0; j < 4; j++) {           // A: 128 rows x 8 units
        int u = tid + j * GT;
        int row = u >> 3, c = u & 7;
        size_t g = ((size_t)row * NFFT + kb + c * 8) * 2;
        uint32_t so = sbase + row * LDA + c * 16;
        CP_ASYNC16(so, Ah + g);
        CP_ASYNC16(so + OFF_ALO, Al + g);
    }
#pragma unroll
    for (int j = 0; j < 6; j++) {           // B: 192 rows x 8 units
        int u = tid + j * GT;
        int row = u >> 3, c = u & 7;
        size_t g = ((size_t)row * NFFT + kb + c * 8) * 2;
        uint32_t so = sbase + OFF_BHI + row * LDA + c * 16;
        CP_ASYNC16(so, Bh + g);
        CP_ASYNC16(so + B_TILE, Bl + g);
    }
}

__global__ void __launch_bounds__(GT, 1) gemm_mma_kernel(
    const float* __restrict__ bias, float* __restrict__ out)
{
    extern __shared__ char smem[];
    const uint32_t sb = smem_u32(smem);
    const int tid = threadIdx.x, wid = tid >> 5, lid = tid & 31;
    const int warp_m = wid & 1, warp_n = wid >> 1;   // 2 x 4 warps
    const int Nbase = blockIdx.x * GBN, Mbase = blockIdx.y * GBM;

    const char* Ah = (const char*)(g_zhi + (size_t)Mbase * NFFT);
    const char* Al = (const char*)(g_zlo + (size_t)Mbase * NFFT);
    const char* Bh = (const char*)(g_whi + (size_t)Nbase * NFFT);
    const char* Bl = (const char*)(g_wlo + (size_t)Nbase * NFFT);

    float acc[4][6][4];
#pragma unroll
    for (int i = 0; i < 4; i++)
#pragma unroll
        for (int j = 0; j < 6; j++)
#pragma unroll
            for (int q = 0; q < 4; q++) acc[i][j][q] = 0.f;

    // per-lane ldmatrix address components
    const int a_row = warp_m * 64 + (lid & 7) + ((lid >> 3) & 1) * 8;  // + mi*16
    const int a_col = ((lid >> 4) & 1) * 16;                            // + ks*32
    const int b_row = warp_n * 48 + ((lid >> 4) & 1) * 8 + (lid & 7);   // + ng*16
    const int b_col = ((lid >> 3) & 1) * 16;                            // + ks*32

    load_chunk(sb, Ah, Al, Bh, Bl, 0, tid);
    CP_COMMIT();

    const int NIT = NFFT / GBK;  // 250
    for (int it = 0; it < NIT; ++it) {
        if (it + 1 < NIT) {
            load_chunk(sb + ((it + 1) & 1) * ST_STRIDE, Ah, Al, Bh, Bl,
                       (it + 1) * GBK, tid);
            CP_COMMIT();
        }
        CP_WAIT1();
        __syncthreads();

        const uint32_t ab = sb + (it & 1) * ST_STRIDE;
#pragma unroll
        for (int ks = 0; ks < 4; ks++) {
            uint32_t ah[4][4], al[4][4], bh[3][4], blo[3][4];
#pragma unroll
            for (int mi = 0; mi < 4; mi++) {
                uint32_t ad = ab + (a_row + mi * 16) * LDA + ks * 32 + a_col;
                ldmx4(ah[mi], ad);
                ldmx4(al[mi], ad + OFF_ALO);
            }
#pragma unroll
            for (int ng = 0; ng < 3; ng++) {
                uint32_t bd = ab + OFF_BHI + (b_row + ng * 16) * LDA + ks * 32 + b_col;
                ldmx4(bh[ng], bd);
                ldmx4(blo[ng], bd + B_TILE);
            }
#pragma unroll
            for (int mi = 0; mi < 4; mi++)
#pragma unroll
                for (int ng = 0; ng < 3; ng++)
#pragma unroll
                    for (int h = 0; h < 2; h++) {
                        float* d = acc[mi][ng * 2 + h];
                        mma_bf16(d, ah[mi], &bh[ng][h * 2]);   // hi*hi
                        mma_bf16(d, al[mi], &bh[ng][h * 2]);   // lo*hi
                        mma_bf16(d, ah[mi], &blo[ng][h * 2]);  // hi*lo
                    }
        }
        __syncthreads();
    }

    // epilogue: bias + relu, fp32 stores (n-tiles fully in/out: 3000 % 8 == 0)
    const int r = lid >> 2, cq = (lid & 3) * 2;
#pragma unroll
    for (int mi = 0; mi < 4; mi++) {
        int m0 = Mbase + warp_m * 64 + mi * 16 + r;
#pragma unroll
        for (int nt = 0; nt < 6; nt++) {
            int n = Nbase + warp_n * 48 + nt * 8 + cq;
            if (n < OUTN) {
                float b0 = __ldg(bias + n), b1 = __ldg(bias + n + 1);
                float2 v0 = make_float2(fmaxf(acc[mi][nt][0] + b0, 0.f),
                                        fmaxf(acc[mi][nt][1] + b1, 0.f));
                float2 v1 = make_float2(fmaxf(acc[mi][nt][2] + b0, 0.f),
                                        fmaxf(acc[mi][nt][3] + b1, 0.f));
                *(float2*)(out + (size_t)m0 * OUTN + n) = v0;
                *(float2*)(out + (size_t)(m0 + 8) * OUTN + n) = v1;
            }
        }
    }
}

// ---------------------------------------------------------------------------
extern "C" void kernel_launch(void* const* d_in, const int* in_sizes, int n_in,
                              void* d_out, int out_size)
{
    const float* x0 = (const float*)d_in[0];
    const float* x1 = (const float*)d_in[1];
    const int* h0 = (const int*)d_in[2];
    const int* h1 = (const int*)d_in[3];
    const int* s0 = (const int*)d_in[4];
    const int* s1 = (const int*)d_in[5];
    const float* W = (const float*)d_in[6];
    const float* bias = (const float*)d_in[7];
    float* out = (float*)d_out;

    twinit_kernel<<<(NFFT + 255) / 256, 256>>>();
    wconv_kernel<<<OUTP, 256>>>(W);

    cudaFuncSetAttribute(fftconv_kernel,
                         cudaFuncAttributeMaxDynamicSharedMemorySize, NFFT * 8);
    fftconv_kernel<<<BATCH, TPB, NFFT * 8>>>(x0, x1, h0, h1, s0, s1);

    cudaFuncSetAttribute(gemm_mma_kernel,
                         cudaFuncAttributeMaxDynamicSharedMemorySize, GSMEM_TOTAL);
    gemm_mma_kernel<<<dim3(OUTP / GBN, BATCH / GBM), GT, GSMEM_TOTAL>>>(bias, out);
}

// round 11
// speedup vs baseline: 1.0020x; 1.0020x over previous
#include <cuda_runtime.h>
#include <cuda_bf16.h>
#include <math.h>
#include <stdint.h>

#define NFFT  16000
#define DIN   2048
#define BATCH 1024
#define OUTN  3000
#define OUTP  3072
#define TPB   512

// ---------------- device globals (no runtime allocation) ----------------
__device__ float2 g_tw[NFFT];                          // W_16000^t = (cos, -sin)
__device__ __nv_bfloat16 g_zhi[BATCH * (size_t)NFFT];
__device__ __nv_bfloat16 g_zlo[BATCH * (size_t)NFFT];
__device__ __nv_bfloat16 g_whi[OUTP * (size_t)NFFT];
__device__ __nv_bfloat16 g_wlo[OUTP * (size_t)NFFT];

// ---------------- helpers ----------------
__device__ __forceinline__ uint32_t smem_u32(const void* p) {
    uint32_t a;
    asm("{ .reg .u64 t; cvta.to.shared.u64 t, %1; cvt.u32.u64 %0, t; }" : "=r"(a) : "l"(p));
    return a;
}
__device__ __forceinline__ int rev7(int x) { return (int)(__brev((unsigned)x) >> 25); }
__device__ __forceinline__ int rev5(int n) {
    int d0 = n % 5; n /= 5; int d1 = n % 5; int d2 = n / 5;
    return d0 * 25 + d1 * 5 + d2;
}
__device__ __forceinline__ float2 cmul(float2 a, float2 b) {
    return make_float2(a.x * b.x - a.y * b.y, a.x * b.y + a.y * b.x);
}

// ---------------- portable tensor-core / async-copy PTX (sm_80+) ----------------
#define CP_ASYNC16(dst, src) \
    asm volatile("cp.async.cg.shared.global [%0], [%1], 16;" :: "r"(dst), "l"(src))
#define CP_COMMIT() asm volatile("cp.async.commit_group;" ::: "memory")
#define CP_WAIT1()  asm volatile("cp.async.wait_group 1;" ::: "memory")

__device__ __forceinline__ void ldmx4(uint32_t* r, uint32_t addr) {
    asm volatile("ldmatrix.sync.aligned.m8n8.x4.shared.b16 {%0,%1,%2,%3}, [%4];"
        : "=r"(r[0]), "=r"(r[1]), "=r"(r[2]), "=r"(r[3]) : "r"(addr));
}
__device__ __forceinline__ void mma_bf16(float* d, const uint32_t* a, const uint32_t* b) {
    asm volatile(
        "mma.sync.aligned.m16n8k16.row.col.f32.bf16.bf16.f32 "
        "{%0,%1,%2,%3}, {%4,%5,%6,%7}, {%8,%9}, {%0,%1,%2,%3};"
        : "+f"(d[0]), "+f"(d[1]), "+f"(d[2]), "+f"(d[3])
        : "r"(a[0]), "r"(a[1]), "r"(a[2]), "r"(a[3]), "r"(b[0]), "r"(b[1]));
}

// ---------------------------------------------------------------------------
// twiddle table init: g_tw[t] = exp(-2 pi i t / 16000)
// ---------------------------------------------------------------------------
__global__ void twinit_kernel() {
    int t = blockIdx.x * blockDim.x + threadIdx.x;
    if (t < NFFT) {
        double s, c;
        sincospi(-(double)t / 8000.0, &s, &c);
        g_tw[t] = make_float2((float)c, (float)s);
    }
}

// ---------------------------------------------------------------------------
// W -> bf16 hi/lo split, padded to OUTP rows (pad rows = 0)
// ---------------------------------------------------------------------------
__global__ void wconv_kernel(const float* __restrict__ W) {
    int row = blockIdx.x;
    const float4* src = (const float4*)(W + (size_t)row * NFFT);
    uint2* dhi = (uint2*)(g_whi + (size_t)row * NFFT);
    uint2* dlo = (uint2*)(g_wlo + (size_t)row * NFFT);
    bool ok = row < OUTN;
    for (int c4 = threadIdx.x; c4 < NFFT / 4; c4 += blockDim.x) {
        float4 v = ok ? __ldg(src + c4) : make_float4(0.f, 0.f, 0.f, 0.f);
        float vv[4] = {v.x, v.y, v.z, v.w};
        unsigned short h[4], l[4];
#pragma unroll
        for (int i = 0; i < 4; i++) {
            __nv_bfloat16 hb = __float2bfloat16(vv[i]);
            __nv_bfloat16 lb = __float2bfloat16(vv[i] - __bfloat162float(hb));
            h[i] = __bfloat16_as_ushort(hb);
            l[i] = __bfloat16_as_ushort(lb);
        }
        uint2 hp, lp;
        hp.x = (uint32_t)h[0] | ((uint32_t)h[1] << 16);
        hp.y = (uint32_t)h[2] | ((uint32_t)h[3] << 16);
        lp.x = (uint32_t)l[0] | ((uint32_t)l[1] << 16);
        lp.y = (uint32_t)l[2] | ((uint32_t)l[3] << 16);
        dhi[c4] = hp;
        dlo[c4] = lp;
    }
}

// ---------------------------------------------------------------------------
// Fused count-sketch + forward FFT(p0 + i p1) + pointwise product + inverse FFT
// (table-driven twiddles). One block per batch row. Output: z as bf16 hi/lo.
// ---------------------------------------------------------------------------
__global__ void __launch_bounds__(TPB, 1) fftconv_kernel(
    const float* __restrict__ x0, const float* __restrict__ x1,
    const int* __restrict__ h0, const int* __restrict__ h1,
    const int* __restrict__ s0, const int* __restrict__ s1)
{
    extern __shared__ float2 sh[];  // 16000 complex = 128000 B
    const int b = blockIdx.x, tid = threadIdx.x;

    for (int i = tid; i < NFFT; i += TPB) sh[i] = make_float2(0.f, 0.f);
    __syncthreads();

    for (int i = tid; i < DIN; i += TPB) {
        int bin = h0[i];
        float v = x0[b * DIN + i] * (float)(2 * s0[i] - 1);
        int addr = rev5(bin % 125) + 125 * rev7(bin / 125);
        atomicAdd(&sh[addr].x, v);
        bin = h1[i];
        v = x1[b * DIN + i] * (float)(2 * s1[i] - 1);
        addr = rev5(bin % 125) + 125 * rev7(bin / 125);
        atomicAdd(&sh[addr].y, v);
    }
    __syncthreads();

    // forward radix-2 DIT over n2 (stride 125)
    for (int len = 2; len <= 128; len <<= 1) {
        int half = len >> 1, step = NFFT / len;
        for (int t = tid; t < 8000; t += TPB) {
            int col = t % 125, bf = t / 125;
            int g = bf / half, pos = bf - g * half;
            int ia = col + 125 * (g * len + pos);
            int ib = ia + 125 * half;
            float2 w = __ldg(&g_tw[pos * step]);
            float2 A = sh[ia], B = sh[ib];
            float tr = B.x * w.x - B.y * w.y;
            float ti = B.x * w.y + B.y * w.x;
            sh[ia] = make_float2(A.x + tr, A.y + ti);
            sh[ib] = make_float2(A.x - tr, A.y - ti);
        }
        __syncthreads();
    }

    // forward mid twiddle W_N^{n1*k2}
    for (int idx = tid; idx < NFFT; idx += TPB) {
        int n1 = rev5(idx % 125), k2 = idx / 125;
        float2 w = __ldg(&g_tw[n1 * k2]);
        sh[idx] = cmul(sh[idx], w);
    }
    __syncthreads();

    const float W5c[5]  = {1.f, 0.30901699f, -0.80901699f, -0.80901699f, 0.30901699f};
    const float W5sF[5] = {0.f, -0.95105652f, -0.58778525f, 0.58778525f, 0.95105652f};
    const float W5sI[5] = {0.f,  0.95105652f,  0.58778525f, -0.58778525f, -0.95105652f};

    // forward radix-5 DIT over n1 (stride 1)
    for (int len = 5; len <= 125; len *= 5) {
        int span = len / 5, step = NFFT / len;
        for (int t = tid; t < 3200; t += TPB) {
            int k2 = t & 127, bf = t >> 7;
            int g = bf / span, pos = bf - g * span;
            int base = 125 * k2 + g * len + pos;
            float2 a[5];
#pragma unroll
            for (int q = 0; q < 5; q++) a[q] = sh[base + q * span];
#pragma unroll
            for (int t5 = 1; t5 < 5; t5++) {
                float2 w = __ldg(&g_tw[pos * t5 * step]);
                a[t5] = cmul(a[t5], w);
            }
#pragma unroll
            for (int q = 0; q < 5; q++) {
                float2 o = a[0];
#pragma unroll
                for (int t5 = 1; t5 < 5; t5++) {
                    int r = (q * t5) % 5;
                    o.x += a[t5].x * W5c[r] - a[t5].y * W5sF[r];
                    o.y += a[t5].x * W5sF[r] + a[t5].y * W5c[r];
                }
                sh[base + q * span] = o;
            }
        }
        __syncthreads();
    }

    // pointwise: separate P0/P1, Z = P0*P1, Hermitian fill
    for (int k = tid; k <= 8000; k += TPB) {
        int kc = (k == 0) ? 0 : (NFFT - k);
        int sA = (k >> 7) + 125 * (k & 127);
        int sB = (kc >> 7) + 125 * (kc & 127);
        float2 FA = sh[sA], FB = sh[sB];
        float p0r = 0.5f * (FA.x + FB.x), p0i = 0.5f * (FA.y - FB.y);
        float p1r = 0.5f * (FA.y + FB.y), p1i = 0.5f * (FB.x - FA.x);
        float zr = p0r * p1r - p0i * p1i;
        float zi = p0r * p1i + p0i * p1r;
        sh[sA] = make_float2(zr, zi);
        if (sB != sA) sh[sB] = make_float2(zr, -zi);
    }
    __syncthreads();

    // inverse radix-5 DIF over k1 (stride 1)
    for (int len = 125; len >= 5; len /= 5) {
        int span = len / 5, step = NFFT / len;
        for (int t = tid; t < 3200; t += TPB) {
            int k2 = t & 127, bf = t >> 7;
            int g = bf / span, pos = bf - g * span;
            int base = 125 * k2 + g * len + pos;
            float2 a[5];
#pragma unroll
            for (int q = 0; q < 5; q++) a[q] = sh[base + q * span];
#pragma unroll
            for (int q = 0; q < 5; q++) {
                float2 o = a[0];
#pragma unroll
                for (int t5 = 1; t5 < 5; t5++) {
                    int r = (q * t5) % 5;
                    o.x += a[t5].x * W5c[r] - a[t5].y * W5sI[r];
                    o.y += a[t5].x * W5sI[r] + a[t5].y * W5c[r];
                }
                float2 w = __ldg(&g_tw[pos * q * step]);
                w.y = -w.y;
                sh[base + q * span] = cmul(o, w);
            }
        }
        __syncthreads();
    }

    // inverse mid twiddle (conjugate)
    for (int idx = tid; idx < NFFT; idx += TPB) {
        int n1 = rev5(idx % 125), k2 = idx / 125;
        float2 w = __ldg(&g_tw[n1 * k2]);
        w.y = -w.y;
        sh[idx] = cmul(sh[idx], w);
    }
    __syncthreads();

    // inverse radix-2 DIF over k2 (stride 125)
    for (int len = 128; len >= 2; len >>= 1) {
        int half = len >> 1, step = NFFT / len;
        for (int t = tid; t < 8000; t += TPB) {
            int col = t % 125, bf = t / 125;
            int g = bf / half, pos = bf - g * half;
            int ia = col + 125 * (g * len + pos);
            int ib = ia + 125 * half;
            float2 A = sh[ia], B = sh[ib];
            float2 sum = make_float2(A.x + B.x, A.y + B.y);
            float2 dif = make_float2(A.x - B.x, A.y - B.y);
            float2 w = __ldg(&g_tw[pos * step]);
            w.y = -w.y;
            sh[ia] = sum;
            sh[ib] = cmul(dif, w);
        }
        __syncthreads();
    }

    // store z as bf16 hi/lo, unpermute, scale 1/N
    for (int n = tid; n < NFFT; n += TPB) {
        int addr = rev5(n % 125) + 125 * rev7(n / 125);
        float zr = sh[addr].x * (1.f / 16000.f);
        __nv_bfloat16 hb = __float2bfloat16(zr);
        g_zhi[b * (size_t)NFFT + n] = hb;
        g_zlo[b * (size_t)NFFT + n] = __float2bfloat16(zr - __bfloat162float(hb));
    }
}

// ---------------------------------------------------------------------------
// GEMM via mma.sync (HMMA, portable PTX): out = relu(z @ W^T + b)
// bf16 split precision, 3 passes (hi*hi + lo*hi + hi*lo), fp32 accumulate.
// CTA tile 128x192, K-chunk 64, cp.async double buffering. Grid 16x8 = 128
// CTAs = one uniform wave on 148 SMs.
// ---------------------------------------------------------------------------
#define GBM 128
#define GBN 192
#define GBK 64
#define GT  256
#define LDA 144                       // smem row pitch bytes (64 bf16 + 8 pad)
#define A_TILE (GBM * LDA)            // 18432
#define B_TILE (GBN * LDA)            // 27648
#define OFF_ALO  A_TILE
#define OFF_BHI  (2 * A_TILE)
#define OFF_BLO  (2 * A_TILE + B_TILE)
#define ST_STRIDE (2 * A_TILE + 2 * B_TILE)   // 92160
#define GSMEM_TOTAL (2 * ST_STRIDE)           // 184320

__device__ __forceinline__ void load_chunk(
    uint32_t sbase, const char* Ah, const char* Al,
    const char* Bh, const char* Bl, int kb, int tid)
{
#pragma unroll
    for (int j = 0; j < 4; j++) {           // A: 128 rows x 8 units
        int u = tid + j * GT;
        int row = u >> 3, c = u & 7;
        size_t g = ((size_t)row * NFFT + kb + c * 8) * 2;
        uint32_t so = sbase + row * LDA + c * 16;
        CP_ASYNC16(so, Ah + g);
        CP_ASYNC16(so + OFF_ALO, Al + g);
    }
#pragma unroll
    for (int j = 0; j < 6; j++) {           // B: 192 rows x 8 units
        int u = tid + j * GT;
        int row = u >> 3, c = u & 7;
        size_t g = ((size_t)row * NFFT + kb + c * 8) * 2;
        uint32_t so = sbase + OFF_BHI + row * LDA + c * 16;
        CP_ASYNC16(so, Bh + g);
        CP_ASYNC16(so + B_TILE, Bl + g);
    }
}

__global__ void __launch_bounds__(GT, 1) gemm_mma_kernel(
    const float* __restrict__ bias, float* __restrict__ out)
{
    extern __shared__ char smem[];
    const uint32_t sb = smem_u32(smem);
    const int tid = threadIdx.x, wid = tid >> 5, lid = tid & 31;
    const int warp_m = wid & 1, warp_n = wid >> 1;   // 2 x 4 warps
    const int Nbase = blockIdx.x * GBN, Mbase = blockIdx.y * GBM;

    const char* Ah = (const char*)(g_zhi + (size_t)Mbase * NFFT);
    const char* Al = (const char*)(g_zlo + (size_t)Mbase * NFFT);
    const char* Bh = (const char*)(g_whi + (size_t)Nbase * NFFT);
    const char* Bl = (const char*)(g_wlo + (size_t)Nbase * NFFT);

    float acc[4][6][4];
#pragma unroll
    for (int i = 0; i < 4; i++)
#pragma unroll
        for (int j = 0; j < 6; j++)
#pragma unroll
            for (int q = 0; q < 4; q++) acc[i][j][q] = 0.f;

    // per-lane ldmatrix address components
    const int a_row = warp_m * 64 + (lid & 7) + ((lid >> 3) & 1) * 8;  // + mi*16
    const int a_col = ((lid >> 4) & 1) * 16;                            // + ks*32
    const int b_row = warp_n * 48 + ((lid >> 4) & 1) * 8 + (lid & 7);   // + ng*16
    const int b_col = ((lid >> 3) & 1) * 16;                            // + ks*32

    load_chunk(sb, Ah, Al, Bh, Bl, 0, tid);
    CP_COMMIT();

    const int NIT = NFFT / GBK;  // 250
    for (int it = 0; it < NIT; ++it) {
        if (it + 1 < NIT) {
            load_chunk(sb + ((it + 1) & 1) * ST_STRIDE, Ah, Al, Bh, Bl,
                       (it + 1) * GBK, tid);
            CP_COMMIT();
        }
        CP_WAIT1();
        __syncthreads();

        const uint32_t ab = sb + (it & 1) * ST_STRIDE;
#pragma unroll
        for (int ks = 0; ks < 4; ks++) {
            uint32_t ah[4][4], al[4][4], bh[3][4], blo[3][4];
#pragma unroll
            for (int mi = 0; mi < 4; mi++) {
                uint32_t ad = ab + (a_row + mi * 16) * LDA + ks * 32 + a_col;
                ldmx4(ah[mi], ad);
                ldmx4(al[mi], ad + OFF_ALO);
            }
#pragma unroll
            for (int ng = 0; ng < 3; ng++) {
                uint32_t bd = ab + OFF_BHI + (b_row + ng * 16) * LDA + ks * 32 + b_col;
                ldmx4(bh[ng], bd);
                ldmx4(blo[ng], bd + B_TILE);
            }
#pragma unroll
            for (int mi = 0; mi < 4; mi++)
#pragma unroll
                for (int ng = 0; ng < 3; ng++)
#pragma unroll
                    for (int h = 0; h < 2; h++) {
                        float* d = acc[mi][ng * 2 + h];
                        mma_bf16(d, ah[mi], &bh[ng][h * 2]);   // hi*hi
                        mma_bf16(d, al[mi], &bh[ng][h * 2]);   // lo*hi
                        mma_bf16(d, ah[mi], &blo[ng][h * 2]);  // hi*lo
                    }
        }
        __syncthreads();
    }

    // epilogue: bias + relu, fp32 stores (n-tiles fully in/out: 3000 % 8 == 0)
    const int r = lid >> 2, cq = (lid & 3) * 2;
#pragma unroll
    for (int mi = 0; mi < 4; mi++) {
        int m0 = Mbase + warp_m * 64 + mi * 16 + r;
#pragma unroll
        for (int nt = 0; nt < 6; nt++) {
            int n = Nbase + warp_n * 48 + nt * 8 + cq;
            if (n < OUTN) {
                float b0 = __ldg(bias + n), b1 = __ldg(bias + n + 1);
                float2 v0 = make_float2(fmaxf(acc[mi][nt][0] + b0, 0.f),
                                        fmaxf(acc[mi][nt][1] + b1, 0.f));
                float2 v1 = make_float2(fmaxf(acc[mi][nt][2] + b0, 0.f),
                                        fmaxf(acc[mi][nt][3] + b1, 0.f));
                *(float2*)(out + (size_t)m0 * OUTN + n) = v0;
                *(float2*)(out + (size_t)(m0 + 8) * OUTN + n) = v1;
            }
        }
    }
}

// ---------------------------------------------------------------------------
extern "C" void kernel_launch(void* const* d_in, const int* in_sizes, int n_in,
                              void* d_out, int out_size)
{
    const float* x0 = (const float*)d_in[0];
    const float* x1 = (const float*)d_in[1];
    const int* h0 = (const int*)d_in[2];
    const int* h1 = (const int*)d_in[3];
    const int* s0 = (const int*)d_in[4];
    const int* s1 = (const int*)d_in[5];
    const float* W = (const float*)d_in[6];
    const float* bias = (const float*)d_in[7];
    float* out = (float*)d_out;

    twinit_kernel<<<(NFFT + 255) / 256, 256>>>();
    wconv_kernel<<<OUTP, 256>>>(W);

    cudaFuncSetAttribute(fftconv_kernel,
                         cudaFuncAttributeMaxDynamicSharedMemorySize, NFFT * 8);
    fftconv_kernel<<<BATCH, TPB, NFFT * 8>>>(x0, x1, h0, h1, s0, s1);

    cudaFuncSetAttribute(gemm_mma_kernel,
                         cudaFuncAttributeMaxDynamicSharedMemorySize, GSMEM_TOTAL);
    gemm_mma_kernel<<<dim3(OUTP / GBN, BATCH / GBM), GT, GSMEM_TOTAL>>>(bias, out);
}

// round 12
// speedup vs baseline: 1.0912x; 1.0890x over previous
#include <cuda_runtime.h>
#include <cuda_bf16.h>
#include <math.h>
#include <stdint.h>

#define NFFT  16000
#define DIN   2048
#define BATCH 1024
#define OUTN  3000
#define OUTP  3072
#define TPB   512

// ---------------- device globals (no runtime allocation) ----------------
__device__ float2 g_tw[NFFT];                          // W_16000^t = (cos, -sin)
__device__ __nv_bfloat16 g_zhi[BATCH * (size_t)NFFT];
__device__ __nv_bfloat16 g_zlo[BATCH * (size_t)NFFT];
__device__ __nv_bfloat16 g_whi[OUTP * (size_t)NFFT];
__device__ __nv_bfloat16 g_wlo[OUTP * (size_t)NFFT];

// ---------------- helpers ----------------
__device__ __forceinline__ uint32_t smem_u32(const void* p) {
    uint32_t a;
    asm("{ .reg .u64 t; cvta.to.shared.u64 t, %1; cvt.u32.u64 %0, t; }" : "=r"(a) : "l"(p));
    return a;
}
__device__ __forceinline__ int rev7(int x) { return (int)(__brev((unsigned)x) >> 25); }
__device__ __forceinline__ int rev5(int n) {
    int d0 = n % 5; n /= 5; int d1 = n % 5; int d2 = n / 5;
    return d0 * 25 + d1 * 5 + d2;
}
__device__ __forceinline__ float2 cmul(float2 a, float2 b) {
    return make_float2(a.x * b.x - a.y * b.y, a.x * b.y + a.y * b.x);
}
__device__ __forceinline__ float2 cmulc(float2 a, float2 b) {  // a * conj(b)
    return make_float2(a.x * b.x + a.y * b.y, a.y * b.x - a.x * b.y);
}
__device__ __forceinline__ float2 cadd(float2 a, float2 b) { return make_float2(a.x + b.x, a.y + b.y); }
__device__ __forceinline__ float2 csub(float2 a, float2 b) { return make_float2(a.x - b.x, a.y - b.y); }

// ---------------- portable tensor-core / async-copy PTX (sm_80+) ----------------
#define CP_ASYNC16(dst, src) \
    asm volatile("cp.async.cg.shared.global [%0], [%1], 16;" :: "r"(dst), "l"(src))
#define CP_COMMIT() asm volatile("cp.async.commit_group;" ::: "memory")
#define CP_WAIT1()  asm volatile("cp.async.wait_group 1;" ::: "memory")

__device__ __forceinline__ void ldmx4(uint32_t* r, uint32_t addr) {
    asm volatile("ldmatrix.sync.aligned.m8n8.x4.shared.b16 {%0,%1,%2,%3}, [%4];"
        : "=r"(r[0]), "=r"(r[1]), "=r"(r[2]), "=r"(r[3]) : "r"(addr));
}
__device__ __forceinline__ void mma_bf16(float* d, const uint32_t* a, const uint32_t* b) {
    asm volatile(
        "mma.sync.aligned.m16n8k16.row.col.f32.bf16.bf16.f32 "
        "{%0,%1,%2,%3}, {%4,%5,%6,%7}, {%8,%9}, {%0,%1,%2,%3};"
        : "+f"(d[0]), "+f"(d[1]), "+f"(d[2]), "+f"(d[3])
        : "r"(a[0]), "r"(a[1]), "r"(a[2]), "r"(a[3]), "r"(b[0]), "r"(b[1]));
}

// ---------------------------------------------------------------------------
// twiddle table init: g_tw[t] = exp(-2 pi i t / 16000)
// ---------------------------------------------------------------------------
__global__ void twinit_kernel() {
    int t = blockIdx.x * blockDim.x + threadIdx.x;
    if (t < NFFT) {
        double s, c;
        sincospi(-(double)t / 8000.0, &s, &c);
        g_tw[t] = make_float2((float)c, (float)s);
    }
}

// ---------------------------------------------------------------------------
// W -> bf16 hi/lo split, padded to OUTP rows (pad rows = 0)
// ---------------------------------------------------------------------------
__global__ void wconv_kernel(const float* __restrict__ W) {
    int row = blockIdx.x;
    const float4* src = (const float4*)(W + (size_t)row * NFFT);
    uint2* dhi = (uint2*)(g_whi + (size_t)row * NFFT);
    uint2* dlo = (uint2*)(g_wlo + (size_t)row * NFFT);
    bool ok = row < OUTN;
    for (int c4 = threadIdx.x; c4 < NFFT / 4; c4 += blockDim.x) {
        float4 v = ok ? __ldg(src + c4) : make_float4(0.f, 0.f, 0.f, 0.f);
        float vv[4] = {v.x, v.y, v.z, v.w};
        unsigned short h[4], l[4];
#pragma unroll
        for (int i = 0; i < 4; i++) {
            __nv_bfloat16 hb = __float2bfloat16(vv[i]);
            __nv_bfloat16 lb = __float2bfloat16(vv[i] - __bfloat162float(hb));
            h[i] = __bfloat16_as_ushort(hb);
            l[i] = __bfloat16_as_ushort(lb);
        }
        uint2 hp, lp;
        hp.x = (uint32_t)h[0] | ((uint32_t)h[1] << 16);
        hp.y = (uint32_t)h[2] | ((uint32_t)h[3] << 16);
        lp.x = (uint32_t)l[0] | ((uint32_t)l[1] << 16);
        lp.y = (uint32_t)l[2] | ((uint32_t)l[3] << 16);
        dhi[c4] = hp;
        dlo[c4] = lp;
    }
}

// ---------------------------------------------------------------------------
// Fused count-sketch + forward FFT(p0 + i p1) + pointwise product + inverse
// FFT. Radix-2 stages fused in register pairs (radix-4 data movement);
// mid twiddles folded into adjacent radix-2 sweeps. One block per batch row.
// ---------------------------------------------------------------------------

// forward DIT fused pair: stage len=L then len=2L (butterflies over n2, stride 125)
__device__ __forceinline__ void fwd_r2_pair(float2* sh, int tid, int L) {
    const int H = L >> 1, s1 = NFFT / L, s2 = (NFFT / 2) / L;
    for (int t = tid; t < 4000; t += TPB) {
        int col = t % 125, q = t / 125;
        int g = q / H, p = q - g * H;
        int base = col + 125 * (g * 2 * L + p);
        float2 v0 = sh[base];
        float2 v1 = sh[base + 125 * H];
        float2 v2 = sh[base + 125 * L];
        float2 v3 = sh[base + 125 * (L + H)];
        float2 w1 = __ldg(&g_tw[p * s1]);
        float2 t1 = cmul(w1, v1), t3 = cmul(w1, v3);
        float2 x0 = cadd(v0, t1), x1 = csub(v0, t1);
        float2 x2 = cadd(v2, t3), x3 = csub(v2, t3);
        float2 w2 = __ldg(&g_tw[p * s2]);
        float2 w2b = __ldg(&g_tw[(p + H) * s2]);
        float2 u2 = cmul(w2, x2), u3 = cmul(w2b, x3);
        sh[base]                 = cadd(x0, u2);
        sh[base + 125 * H]       = cadd(x1, u3);
        sh[base + 125 * L]       = csub(x0, u2);
        sh[base + 125 * (L + H)] = csub(x1, u3);
    }
    __syncthreads();
}

// inverse DIF fused pair: stage len=2L then len=L. midfold: multiply inputs
// by conj(tw[n1*k2]) (only for the first pair, 2L = 128).
__device__ __forceinline__ void inv_r2_pair(float2* sh, int tid, int L, bool midfold) {
    const int H = L >> 1, s1 = NFFT / L, s2 = (NFFT / 2) / L;
    for (int t = tid; t < 4000; t += TPB) {
        int col = t % 125, q = t / 125;
        int g = q / H, p = q - g * H;
        int base = col + 125 * (g * 2 * L + p);
        float2 v0 = sh[base];
        float2 v1 = sh[base + 125 * H];
        float2 v2 = sh[base + 125 * L];
        float2 v3 = sh[base + 125 * (L + H)];
        if (midfold) {  // 2L == 128: g == 0, positions p, p+H, p+L, p+L+H
            int n1 = rev5(col);
            v0 = cmulc(v0, __ldg(&g_tw[n1 * p]));
            v1 = cmulc(v1, __ldg(&g_tw[n1 * (p + H)]));
            v2 = cmulc(v2, __ldg(&g_tw[n1 * (p + L)]));
            v3 = cmulc(v3, __ldg(&g_tw[n1 * (p + L + H)]));
        }
        float2 w2a = __ldg(&g_tw[p * s2]);
        float2 w2b = __ldg(&g_tw[(p + H) * s2]);
        float2 y0 = cadd(v0, v2), y2 = cmulc(csub(v0, v2), w2a);
        float2 y1 = cadd(v1, v3), y3 = cmulc(csub(v1, v3), w2b);
        float2 w1 = __ldg(&g_tw[p * s1]);
        sh[base]                 = cadd(y0, y1);
        sh[base + 125 * H]       = cmulc(csub(y0, y1), w1);
        sh[base + 125 * L]       = cadd(y2, y3);
        sh[base + 125 * (L + H)] = cmulc(csub(y2, y3), w1);
    }
    __syncthreads();
}

__global__ void __launch_bounds__(TPB, 1) fftconv_kernel(
    const float* __restrict__ x0, const float* __restrict__ x1,
    const int* __restrict__ h0, const int* __restrict__ h1,
    const int* __restrict__ s0, const int* __restrict__ s1)
{
    extern __shared__ float2 sh[];  // 16000 complex = 128000 B
    const int b = blockIdx.x, tid = threadIdx.x;

    for (int i = tid; i < NFFT; i += TPB) sh[i] = make_float2(0.f, 0.f);
    __syncthreads();

    // scatter count sketches (p0 -> re, p1 -> im), pre-permuted addresses
    for (int i = tid; i < DIN; i += TPB) {
        int bin = h0[i];
        float v = x0[b * DIN + i] * (float)(2 * s0[i] - 1);
        int addr = rev5(bin % 125) + 125 * rev7(bin / 125);
        atomicAdd(&sh[addr].x, v);
        bin = h1[i];
        v = x1[b * DIN + i] * (float)(2 * s1[i] - 1);
        addr = rev5(bin % 125) + 125 * rev7(bin / 125);
        atomicAdd(&sh[addr].y, v);
    }
    __syncthreads();

    // ---- forward radix-2 DIT: fused (2,4), (8,16), (32,64) ----
    fwd_r2_pair(sh, tid, 2);
    fwd_r2_pair(sh, tid, 8);
    fwd_r2_pair(sh, tid, 32);

    // ---- forward single stage len=128 with mid-twiddle fold ----
    for (int t = tid; t < 8000; t += TPB) {
        int col = t % 125, pos = t / 125;
        int ia = col + 125 * pos, ib = ia + 125 * 64;
        float2 w = __ldg(&g_tw[pos * 125]);
        float2 A = sh[ia], B = sh[ib];
        float2 tb = cmul(w, B);
        float2 o0 = cadd(A, tb), o1 = csub(A, tb);
        int n1 = rev5(col);
        sh[ia] = cmul(o0, __ldg(&g_tw[n1 * pos]));
        sh[ib] = cmul(o1, __ldg(&g_tw[n1 * (pos + 64)]));
    }
    __syncthreads();

    const float W5c[5]  = {1.f, 0.30901699f, -0.80901699f, -0.80901699f, 0.30901699f};
    const float W5sF[5] = {0.f, -0.95105652f, -0.58778525f, 0.58778525f, 0.95105652f};
    const float W5sI[5] = {0.f,  0.95105652f,  0.58778525f, -0.58778525f, -0.95105652f};

    // ---- forward radix-5 DIT over n1 (stride 1) ----
    for (int len = 5; len <= 125; len *= 5) {
        int span = len / 5, step = NFFT / len;
        for (int t = tid; t < 3200; t += TPB) {
            int k2 = t & 127, bf = t >> 7;
            int g = bf / span, pos = bf - g * span;
            int base = 125 * k2 + g * len + pos;
            float2 a[5];
#pragma unroll
            for (int q = 0; q < 5; q++) a[q] = sh[base + q * span];
#pragma unroll
            for (int t5 = 1; t5 < 5; t5++) {
                float2 w = __ldg(&g_tw[pos * t5 * step]);
                a[t5] = cmul(a[t5], w);
            }
#pragma unroll
            for (int q = 0; q < 5; q++) {
                float2 o = a[0];
#pragma unroll
                for (int t5 = 1; t5 < 5; t5++) {
                    int r = (q * t5) % 5;
                    o.x += a[t5].x * W5c[r] - a[t5].y * W5sF[r];
                    o.y += a[t5].x * W5sF[r] + a[t5].y * W5c[r];
                }
                sh[base + q * span] = o;
            }
        }
        __syncthreads();
    }

    // ---- pointwise: separate P0/P1, Z = P0*P1, Hermitian fill ----
    for (int k = tid; k <= 8000; k += TPB) {
        int kc = (k == 0) ? 0 : (NFFT - k);
        int sA = (k >> 7) + 125 * (k & 127);
        int sB = (kc >> 7) + 125 * (kc & 127);
        float2 FA = sh[sA], FB = sh[sB];
        float p0r = 0.5f * (FA.x + FB.x), p0i = 0.5f * (FA.y - FB.y);
        float p1r = 0.5f * (FA.y + FB.y), p1i = 0.5f * (FB.x - FA.x);
        float zr = p0r * p1r - p0i * p1i;
        float zi = p0r * p1i + p0i * p1r;
        sh[sA] = make_float2(zr, zi);
        if (sB != sA) sh[sB] = make_float2(zr, -zi);
    }
    __syncthreads();

    // ---- inverse radix-5 DIF over k1 (stride 1) ----
    for (int len = 125; len >= 5; len /= 5) {
        int span = len / 5, step = NFFT / len;
        for (int t = tid; t < 3200; t += TPB) {
            int k2 = t & 127, bf = t >> 7;
            int g = bf / span, pos = bf - g * span;
            int base = 125 * k2 + g * len + pos;
            float2 a[5];
#pragma unroll
            for (int q = 0; q < 5; q++) a[q] = sh[base + q * span];
#pragma unroll
            for (int q = 0; q < 5; q++) {
                float2 o = a[0];
#pragma unroll
                for (int t5 = 1; t5 < 5; t5++) {
                    int r = (q * t5) % 5;
                    o.x += a[t5].x * W5c[r] - a[t5].y * W5sI[r];
                    o.y += a[t5].x * W5sI[r] + a[t5].y * W5c[r];
                }
                float2 w = __ldg(&g_tw[pos * q * step]);
                w.y = -w.y;
                sh[base + q * span] = cmul(o, w);
            }
        }
        __syncthreads();
    }

    // ---- inverse radix-2 DIF: fused (128,64) w/ mid fold, (32,16), (8,4) ----
    inv_r2_pair(sh, tid, 64, true);
    inv_r2_pair(sh, tid, 16, false);
    inv_r2_pair(sh, tid, 4, false);

    // ---- inverse single stage len=2 (twiddle = 1) ----
    for (int t = tid; t < 8000; t += TPB) {
        int col = t % 125, bfi = t / 125;
        int ia = col + 125 * (2 * bfi), ib = ia + 125;
        float2 A = sh[ia], B = sh[ib];
        sh[ia] = cadd(A, B);
        sh[ib] = csub(A, B);
    }
    __syncthreads();

    // ---- store z as bf16 hi/lo, unpermute, scale 1/N ----
    for (int n = tid; n < NFFT; n += TPB) {
        int addr = rev5(n % 125) + 125 * rev7(n / 125);
        float zr = sh[addr].x * (1.f / 16000.f);
        __nv_bfloat16 hb = __float2bfloat16(zr);
        g_zhi[b * (size_t)NFFT + n] = hb;
        g_zlo[b * (size_t)NFFT + n] = __float2bfloat16(zr - __bfloat162float(hb));
    }
}

// ---------------------------------------------------------------------------
// GEMM via mma.sync (HMMA): out = relu(z @ W^T + b)
// bf16 split precision, 3 passes (hi*hi + lo*hi + hi*lo), fp32 accumulate.
// CTA tile 128x192, K-chunk 64, cp.async double buffering, 12 warps
// (2m x 6n, warp tile 64x32). Grid 16x8 = 128 CTAs = one wave.
// ---------------------------------------------------------------------------
#define GBM 128
#define GBN 192
#define GBK 64
#define GT  384
#define LDA 144                       // smem row pitch bytes (64 bf16 + 8 pad)
#define A_TILE (GBM * LDA)            // 18432
#define B_TILE (GBN * LDA)            // 27648
#define OFF_ALO  A_TILE
#define OFF_BHI  (2 * A_TILE)
#define OFF_BLO  (2 * A_TILE + B_TILE)
#define ST_STRIDE (2 * A_TILE + 2 * B_TILE)   // 92160
#define GSMEM_TOTAL (2 * ST_STRIDE)           // 184320

__device__ __forceinline__ void load_chunk(
    uint32_t sbase, const char* Ah, const char* Al,
    const char* Bh, const char* Bl, int kb, int tid)
{
#pragma unroll
    for (int j = 0; j < 3; j++) {           // A: 128 rows x 8 units (1024)
        int u = tid + j * GT;
        if (u < GBM * 8) {
            int row = u >> 3, c = u & 7;
            size_t g = ((size_t)row * NFFT + kb + c * 8) * 2;
            uint32_t so = sbase + row * LDA + c * 16;
            CP_ASYNC16(so, Ah + g);
            CP_ASYNC16(so + OFF_ALO, Al + g);
        }
    }
#pragma unroll
    for (int j = 0; j < 4; j++) {           // B: 192 rows x 8 units (1536)
        int u = tid + j * GT;
        int row = u >> 3, c = u & 7;
        size_t g = ((size_t)row * NFFT + kb + c * 8) * 2;
        uint32_t so = sbase + OFF_BHI + row * LDA + c * 16;
        CP_ASYNC16(so, Bh + g);
        CP_ASYNC16(so + B_TILE, Bl + g);
    }
}

__global__ void __launch_bounds__(GT, 1) gemm_mma_kernel(
    const float* __restrict__ bias, float* __restrict__ out)
{
    extern __shared__ char smem[];
    const uint32_t sb = smem_u32(smem);
    const int tid = threadIdx.x, wid = tid >> 5, lid = tid & 31;
    const int warp_m = wid & 1, warp_n = wid >> 1;   // 2 x 6 warps
    const int Nbase = blockIdx.x * GBN, Mbase = blockIdx.y * GBM;

    const char* Ah = (const char*)(g_zhi + (size_t)Mbase * NFFT);
    const char* Al = (const char*)(g_zlo + (size_t)Mbase * NFFT);
    const char* Bh = (const char*)(g_whi + (size_t)Nbase * NFFT);
    const char* Bl = (const char*)(g_wlo + (size_t)Nbase * NFFT);

    float acc[4][4][4];
#pragma unroll
    for (int i = 0; i < 4; i++)
#pragma unroll
        for (int j = 0; j < 4; j++)
#pragma unroll
            for (int q = 0; q < 4; q++) acc[i][j][q] = 0.f;

    // per-lane ldmatrix address components
    const int a_row = warp_m * 64 + (lid & 7) + ((lid >> 3) & 1) * 8;  // + mi*16
    const int a_col = ((lid >> 4) & 1) * 16;                            // + ks*32
    const int b_row = warp_n * 32 + ((lid >> 4) & 1) * 8 + (lid & 7);   // + ng*16
    const int b_col = ((lid >> 3) & 1) * 16;                            // + ks*32

    load_chunk(sb, Ah, Al, Bh, Bl, 0, tid);
    CP_COMMIT();

    const int NIT = NFFT / GBK;  // 250
    for (int it = 0; it < NIT; ++it) {
        if (it + 1 < NIT) {
            load_chunk(sb + ((it + 1) & 1) * ST_STRIDE, Ah, Al, Bh, Bl,
                       (it + 1) * GBK, tid);
            CP_COMMIT();
        }
        CP_WAIT1();
        __syncthreads();

        const uint32_t ab = sb + (it & 1) * ST_STRIDE;
#pragma unroll
        for (int ks = 0; ks < 4; ks++) {
            uint32_t ah[4][4], al[4][4], bh[2][4], blo[2][4];
#pragma unroll
            for (int mi = 0; mi < 4; mi++) {
                uint32_t ad = ab + (a_row + mi * 16) * LDA + ks * 32 + a_col;
                ldmx4(ah[mi], ad);
                ldmx4(al[mi], ad + OFF_ALO);
            }
#pragma unroll
            for (int ng = 0; ng < 2; ng++) {
                uint32_t bd = ab + OFF_BHI + (b_row + ng * 16) * LDA + ks * 32 + b_col;
                ldmx4(bh[ng], bd);
                ldmx4(blo[ng], bd + B_TILE);
            }
#pragma unroll
            for (int mi = 0; mi < 4; mi++)
#pragma unroll
                for (int ng = 0; ng < 2; ng++)
#pragma unroll
                    for (int h = 0; h < 2; h++) {
                        float* d = acc[mi][ng * 2 + h];
                        mma_bf16(d, ah[mi], &bh[ng][h * 2]);   // hi*hi
                        mma_bf16(d, al[mi], &bh[ng][h * 2]);   // lo*hi
                        mma_bf16(d, ah[mi], &blo[ng][h * 2]);  // hi*lo
                    }
        }
        __syncthreads();
    }

    // epilogue: bias + relu, fp32 stores
    const int r = lid >> 2, cq = (lid & 3) * 2;
#pragma unroll
    for (int mi = 0; mi < 4; mi++) {
        int m0 = Mbase + warp_m * 64 + mi * 16 + r;
#pragma unroll
        for (int nt = 0; nt < 4; nt++) {
            int n = Nbase + warp_n * 32 + nt * 8 + cq;
            if (n < OUTN) {
                float b0 = __ldg(bias + n), b1 = __ldg(bias + n + 1);
                float2 v0 = make_float2(fmaxf(acc[mi][nt][0] + b0, 0.f),
                                        fmaxf(acc[mi][nt][1] + b1, 0.f));
                float2 v1 = make_float2(fmaxf(acc[mi][nt][2] + b0, 0.f),
                                        fmaxf(acc[mi][nt][3] + b1, 0.f));
                *(float2*)(out + (size_t)m0 * OUTN + n) = v0;
                *(float2*)(out + (size_t)(m0 + 8) * OUTN + n) = v1;
            }
        }
    }
}

// ---------------------------------------------------------------------------
extern "C" void kernel_launch(void* const* d_in, const int* in_sizes, int n_in,
                              void* d_out, int out_size)
{
    const float* x0 = (const float*)d_in[0];
    const float* x1 = (const float*)d_in[1];
    const int* h0 = (const int*)d_in[2];
    const int* h1 = (const int*)d_in[3];
    const int* s0 = (const int*)d_in[4];
    const int* s1 = (const int*)d_in[5];
    const float* W = (const float*)d_in[6];
    const float* bias = (const float*)d_in[7];
    float* out = (float*)d_out;

    twinit_kernel<<<(NFFT + 255) / 256, 256>>>();
    wconv_kernel<<<OUTP, 256>>>(W);

    cudaFuncSetAttribute(fftconv_kernel,
                         cudaFuncAttributeMaxDynamicSharedMemorySize, NFFT * 8);
    fftconv_kernel<<<BATCH, TPB, NFFT * 8>>>(x0, x1, h0, h1, s0, s1);

    cudaFuncSetAttribute(gemm_mma_kernel,
                         cudaFuncAttributeMaxDynamicSharedMemorySize, GSMEM_TOTAL);
    gemm_mma_kernel<<<dim3(OUTP / GBN, BATCH / GBM), GT, GSMEM_TOTAL>>>(bias, out);
}

// round 13
// speedup vs baseline: 1.4044x; 1.2870x over previous
#include <cuda_runtime.h>
#include <cuda_fp16.h>
#include <math.h>
#include <stdint.h>

#define NFFT  16000
#define DIN   2048
#define BATCH 1024
#define OUTN  3000
#define OUTP  3072
#define TPB   512

// ---------------- device globals (no runtime allocation) ----------------
__device__ float2 g_tw[NFFT];                      // W_16000^t = (cos, -sin)
__device__ __half g_zhi[BATCH * (size_t)NFFT];
__device__ __half g_zlo[BATCH * (size_t)NFFT];
__device__ __half g_w16[OUTP * (size_t)NFFT];

// ---------------- helpers ----------------
__device__ __forceinline__ uint32_t smem_u32(const void* p) {
    uint32_t a;
    asm("{ .reg .u64 t; cvta.to.shared.u64 t, %1; cvt.u32.u64 %0, t; }" : "=r"(a) : "l"(p));
    return a;
}
__device__ __forceinline__ int rev7(int x) { return (int)(__brev((unsigned)x) >> 25); }
__device__ __forceinline__ int rev5(int n) {
    int d0 = n % 5; n /= 5; int d1 = n % 5; int d2 = n / 5;
    return d0 * 25 + d1 * 5 + d2;
}
__device__ __forceinline__ float2 cmul(float2 a, float2 b) {
    return make_float2(a.x * b.x - a.y * b.y, a.x * b.y + a.y * b.x);
}
__device__ __forceinline__ float2 cmulc(float2 a, float2 b) {  // a * conj(b)
    return make_float2(a.x * b.x + a.y * b.y, a.y * b.x - a.x * b.y);
}
__device__ __forceinline__ float2 cadd(float2 a, float2 b) { return make_float2(a.x + b.x, a.y + b.y); }
__device__ __forceinline__ float2 csub(float2 a, float2 b) { return make_float2(a.x - b.x, a.y - b.y); }

// ---------------- portable tensor-core / async-copy PTX (sm_80+) ----------------
#define CP_ASYNC16(dst, src) \
    asm volatile("cp.async.cg.shared.global [%0], [%1], 16;" :: "r"(dst), "l"(src))
#define CP_COMMIT() asm volatile("cp.async.commit_group;" ::: "memory")
#define CP_WAIT2()  asm volatile("cp.async.wait_group 2;" ::: "memory")

__device__ __forceinline__ void ldmx4(uint32_t* r, uint32_t addr) {
    asm volatile("ldmatrix.sync.aligned.m8n8.x4.shared.b16 {%0,%1,%2,%3}, [%4];"
        : "=r"(r[0]), "=r"(r[1]), "=r"(r[2]), "=r"(r[3]) : "r"(addr));
}
__device__ __forceinline__ void mma_fp16(float* d, const uint32_t* a, const uint32_t* b) {
    asm volatile(
        "mma.sync.aligned.m16n8k16.row.col.f32.f16.f16.f32 "
        "{%0,%1,%2,%3}, {%4,%5,%6,%7}, {%8,%9}, {%0,%1,%2,%3};"
        : "+f"(d[0]), "+f"(d[1]), "+f"(d[2]), "+f"(d[3])
        : "r"(a[0]), "r"(a[1]), "r"(a[2]), "r"(a[3]), "r"(b[0]), "r"(b[1]));
}

// ---------------------------------------------------------------------------
// twiddle table init: g_tw[t] = exp(-2 pi i t / 16000)
// ---------------------------------------------------------------------------
__global__ void twinit_kernel() {
    int t = blockIdx.x * blockDim.x + threadIdx.x;
    if (t < NFFT) {
        double s, c;
        sincospi(-(double)t / 8000.0, &s, &c);
        g_tw[t] = make_float2((float)c, (float)s);
    }
}

// ---------------------------------------------------------------------------
// W -> fp16, padded to OUTP rows (pad rows = 0)
// ---------------------------------------------------------------------------
__global__ void wconv_kernel(const float* __restrict__ W) {
    int row = blockIdx.x;
    const float4* src = (const float4*)(W + (size_t)row * NFFT);
    uint2* dst = (uint2*)(g_w16 + (size_t)row * NFFT);
    bool ok = row < OUTN;
    for (int c4 = threadIdx.x; c4 < NFFT / 4; c4 += blockDim.x) {
        float4 v = ok ? __ldg(src + c4) : make_float4(0.f, 0.f, 0.f, 0.f);
        __half2 lo2 = __floats2half2_rn(v.x, v.y);
        __half2 hi2 = __floats2half2_rn(v.z, v.w);
        uint2 p;
        p.x = *(const uint32_t*)&lo2;
        p.y = *(const uint32_t*)&hi2;
        dst[c4] = p;
    }
}

// ---------------------------------------------------------------------------
// Fused count-sketch + forward FFT(p0 + i p1) + pointwise product + inverse
// FFT. Radix-2 stages fused in register pairs; mid twiddles folded into
// adjacent radix-2 sweeps. One block per batch row. Output: z as fp16 hi/lo.
// ---------------------------------------------------------------------------

// forward DIT fused pair: stage len=L then len=2L (butterflies over n2, stride 125)
__device__ __forceinline__ void fwd_r2_pair(float2* sh, int tid, int L) {
    const int H = L >> 1, s1 = NFFT / L, s2 = (NFFT / 2) / L;
    for (int t = tid; t < 4000; t += TPB) {
        int col = t % 125, q = t / 125;
        int g = q / H, p = q - g * H;
        int base = col + 125 * (g * 2 * L + p);
        float2 v0 = sh[base];
        float2 v1 = sh[base + 125 * H];
        float2 v2 = sh[base + 125 * L];
        float2 v3 = sh[base + 125 * (L + H)];
        float2 w1 = __ldg(&g_tw[p * s1]);
        float2 t1 = cmul(w1, v1), t3 = cmul(w1, v3);
        float2 x0 = cadd(v0, t1), x1 = csub(v0, t1);
        float2 x2 = cadd(v2, t3), x3 = csub(v2, t3);
        float2 w2 = __ldg(&g_tw[p * s2]);
        float2 w2b = __ldg(&g_tw[(p + H) * s2]);
        float2 u2 = cmul(w2, x2), u3 = cmul(w2b, x3);
        sh[base]                 = cadd(x0, u2);
        sh[base + 125 * H]       = cadd(x1, u3);
        sh[base + 125 * L]       = csub(x0, u2);
        sh[base + 125 * (L + H)] = csub(x1, u3);
    }
    __syncthreads();
}

// inverse DIF fused pair: stage len=2L then len=L. midfold: multiply inputs
// by conj(tw[n1*k2]) (only for the first pair, 2L = 128).
__device__ __forceinline__ void inv_r2_pair(float2* sh, int tid, int L, bool midfold) {
    const int H = L >> 1, s1 = NFFT / L, s2 = (NFFT / 2) / L;
    for (int t = tid; t < 4000; t += TPB) {
        int col = t % 125, q = t / 125;
        int g = q / H, p = q - g * H;
        int base = col + 125 * (g * 2 * L + p);
        float2 v0 = sh[base];
        float2 v1 = sh[base + 125 * H];
        float2 v2 = sh[base + 125 * L];
        float2 v3 = sh[base + 125 * (L + H)];
        if (midfold) {  // 2L == 128: g == 0, positions p, p+H, p+L, p+L+H
            int n1 = rev5(col);
            v0 = cmulc(v0, __ldg(&g_tw[n1 * p]));
            v1 = cmulc(v1, __ldg(&g_tw[n1 * (p + H)]));
            v2 = cmulc(v2, __ldg(&g_tw[n1 * (p + L)]));
            v3 = cmulc(v3, __ldg(&g_tw[n1 * (p + L + H)]));
        }
        float2 w2a = __ldg(&g_tw[p * s2]);
        float2 w2b = __ldg(&g_tw[(p + H) * s2]);
        float2 y0 = cadd(v0, v2), y2 = cmulc(csub(v0, v2), w2a);
        float2 y1 = cadd(v1, v3), y3 = cmulc(csub(v1, v3), w2b);
        float2 w1 = __ldg(&g_tw[p * s1]);
        sh[base]                 = cadd(y0, y1);
        sh[base + 125 * H]       = cmulc(csub(y0, y1), w1);
        sh[base + 125 * L]       = cadd(y2, y3);
        sh[base + 125 * (L + H)] = cmulc(csub(y2, y3), w1);
    }
    __syncthreads();
}

__global__ void __launch_bounds__(TPB, 1) fftconv_kernel(
    const float* __restrict__ x0, const float* __restrict__ x1,
    const int* __restrict__ h0, const int* __restrict__ h1,
    const int* __restrict__ s0, const int* __restrict__ s1)
{
    extern __shared__ float2 sh[];  // 16000 complex = 128000 B
    const int b = blockIdx.x, tid = threadIdx.x;

    for (int i = tid; i < NFFT; i += TPB) sh[i] = make_float2(0.f, 0.f);
    __syncthreads();

    // scatter count sketches (p0 -> re, p1 -> im), pre-permuted addresses
    for (int i = tid; i < DIN; i += TPB) {
        int bin = h0[i];
        float v = x0[b * DIN + i] * (float)(2 * s0[i] - 1);
        int addr = rev5(bin % 125) + 125 * rev7(bin / 125);
        atomicAdd(&sh[addr].x, v);
        bin = h1[i];
        v = x1[b * DIN + i] * (float)(2 * s1[i] - 1);
        addr = rev5(bin % 125) + 125 * rev7(bin / 125);
        atomicAdd(&sh[addr].y, v);
    }
    __syncthreads();

    // ---- forward radix-2 DIT: fused (2,4), (8,16), (32,64) ----
    fwd_r2_pair(sh, tid, 2);
    fwd_r2_pair(sh, tid, 8);
    fwd_r2_pair(sh, tid, 32);

    // ---- forward single stage len=128 with mid-twiddle fold ----
    for (int t = tid; t < 8000; t += TPB) {
        int col = t % 125, pos = t / 125;
        int ia = col + 125 * pos, ib = ia + 125 * 64;
        float2 w = __ldg(&g_tw[pos * 125]);
        float2 A = sh[ia], B = sh[ib];
        float2 tb = cmul(w, B);
        float2 o0 = cadd(A, tb), o1 = csub(A, tb);
        int n1 = rev5(col);
        sh[ia] = cmul(o0, __ldg(&g_tw[n1 * pos]));
        sh[ib] = cmul(o1, __ldg(&g_tw[n1 * (pos + 64)]));
    }
    __syncthreads();

    const float W5c[5]  = {1.f, 0.30901699f, -0.80901699f, -0.80901699f, 0.30901699f};
    const float W5sF[5] = {0.f, -0.95105652f, -0.58778525f, 0.58778525f, 0.95105652f};
    const float W5sI[5] = {0.f,  0.95105652f,  0.58778525f, -0.58778525f, -0.95105652f};

    // ---- forward radix-5 DIT over n1 (stride 1) ----
    for (int len = 5; len <= 125; len *= 5) {
        int span = len / 5, step = NFFT / len;
        for (int t = tid; t < 3200; t += TPB) {
            int k2 = t & 127, bf = t >> 7;
            int g = bf / span, pos = bf - g * span;
            int base = 125 * k2 + g * len + pos;
            float2 a[5];
#pragma unroll
            for (int q = 0; q < 5; q++) a[q] = sh[base + q * span];
#pragma unroll
            for (int t5 = 1; t5 < 5; t5++) {
                float2 w = __ldg(&g_tw[pos * t5 * step]);
                a[t5] = cmul(a[t5], w);
            }
#pragma unroll
            for (int q = 0; q < 5; q++) {
                float2 o = a[0];
#pragma unroll
                for (int t5 = 1; t5 < 5; t5++) {
                    int r = (q * t5) % 5;
                    o.x += a[t5].x * W5c[r] - a[t5].y * W5sF[r];
                    o.y += a[t5].x * W5sF[r] + a[t5].y * W5c[r];
                }
                sh[base + q * span] = o;
            }
        }
        __syncthreads();
    }

    // ---- pointwise: separate P0/P1, Z = P0*P1, Hermitian fill ----
    for (int k = tid; k <= 8000; k += TPB) {
        int kc = (k == 0) ? 0 : (NFFT - k);
        int sA = (k >> 7) + 125 * (k & 127);
        int sB = (kc >> 7) + 125 * (kc & 127);
        float2 FA = sh[sA], FB = sh[sB];
        float p0r = 0.5f * (FA.x + FB.x), p0i = 0.5f * (FA.y - FB.y);
        float p1r = 0.5f * (FA.y + FB.y), p1i = 0.5f * (FB.x - FA.x);
        float zr = p0r * p1r - p0i * p1i;
        float zi = p0r * p1i + p0i * p1r;
        sh[sA] = make_float2(zr, zi);
        if (sB != sA) sh[sB] = make_float2(zr, -zi);
    }
    __syncthreads();

    // ---- inverse radix-5 DIF over k1 (stride 1) ----
    for (int len = 125; len >= 5; len /= 5) {
        int span = len / 5, step = NFFT / len;
        for (int t = tid; t < 3200; t += TPB) {
            int k2 = t & 127, bf = t >> 7;
            int g = bf / span, pos = bf - g * span;
            int base = 125 * k2 + g * len + pos;
            float2 a[5];
#pragma unroll
            for (int q = 0; q < 5; q++) a[q] = sh[base + q * span];
#pragma unroll
            for (int q = 0; q < 5; q++) {
                float2 o = a[0];
#pragma unroll
                for (int t5 = 1; t5 < 5; t5++) {
                    int r = (q * t5) % 5;
                    o.x += a[t5].x * W5c[r] - a[t5].y * W5sI[r];
                    o.y += a[t5].x * W5sI[r] + a[t5].y * W5c[r];
                }
                float2 w = __ldg(&g_tw[pos * q * step]);
                w.y = -w.y;
                sh[base + q * span] = cmul(o, w);
            }
        }
        __syncthreads();
    }

    // ---- inverse radix-2 DIF: fused (128,64) w/ mid fold, (32,16), (8,4) ----
    inv_r2_pair(sh, tid, 64, true);
    inv_r2_pair(sh, tid, 16, false);
    inv_r2_pair(sh, tid, 4, false);

    // ---- inverse single stage len=2 (twiddle = 1) ----
    for (int t = tid; t < 8000; t += TPB) {
        int col = t % 125, bfi = t / 125;
        int ia = col + 125 * (2 * bfi), ib = ia + 125;
        float2 A = sh[ia], B = sh[ib];
        sh[ia] = cadd(A, B);
        sh[ib] = csub(A, B);
    }
    __syncthreads();

    // ---- store z as fp16 hi/lo, unpermute, scale 1/N ----
    for (int n = tid; n < NFFT; n += TPB) {
        int addr = rev5(n % 125) + 125 * rev7(n / 125);
        float zr = sh[addr].x * (1.f / 16000.f);
        __half hb = __float2half_rn(zr);
        g_zhi[b * (size_t)NFFT + n] = hb;
        g_zlo[b * (size_t)NFFT + n] = __float2half_rn(zr - __half2float(hb));
    }
}

// ---------------------------------------------------------------------------
// GEMM via mma.sync (HMMA fp16): out = relu(z @ W^T + b)
// fp16 split-A 2-pass (zhi*W + zlo*W), fp32 accumulate.
// CTA tile 128x192, K-chunk 64, 3-stage cp.async pipeline, 12 warps
// (2m x 6n, warp tile 64x32). Grid 16x8 = 128 CTAs = one wave.
// ---------------------------------------------------------------------------
#define GBM 128
#define GBN 192
#define GBK 64
#define GT  384
#define LDA 144                       // smem row pitch bytes (64 fp16 + 8 pad)
#define A_TILE (GBM * LDA)            // 18432
#define B_TILE (GBN * LDA)            // 27648
#define OFF_ALO  A_TILE
#define OFF_B    (2 * A_TILE)
#define ST_STRIDE (2 * A_TILE + B_TILE)       // 64512
#define GSMEM_TOTAL (3 * ST_STRIDE)           // 193536

__device__ __forceinline__ void load_chunk(
    uint32_t sbase, const char* Ah, const char* Al, const char* Bw,
    int kb, int tid)
{
#pragma unroll
    for (int j = 0; j < 3; j++) {           // A: 128 rows x 8 units (1024)
        int u = tid + j * GT;
        if (u < GBM * 8) {
            int row = u >> 3, c = u & 7;
            size_t g = ((size_t)row * NFFT + kb + c * 8) * 2;
            uint32_t so = sbase + row * LDA + c * 16;
            CP_ASYNC16(so, Ah + g);
            CP_ASYNC16(so + OFF_ALO, Al + g);
        }
    }
#pragma unroll
    for (int j = 0; j < 4; j++) {           // B: 192 rows x 8 units (1536)
        int u = tid + j * GT;
        int row = u >> 3, c = u & 7;
        size_t g = ((size_t)row * NFFT + kb + c * 8) * 2;
        uint32_t so = sbase + OFF_B + row * LDA + c * 16;
        CP_ASYNC16(so, Bw + g);
    }
}

__global__ void __launch_bounds__(GT, 1) gemm_mma_kernel(
    const float* __restrict__ bias, float* __restrict__ out)
{
    extern __shared__ char smem[];
    const uint32_t sb = smem_u32(smem);
    const int tid = threadIdx.x, wid = tid >> 5, lid = tid & 31;
    const int warp_m = wid & 1, warp_n = wid >> 1;   // 2 x 6 warps
    const int Nbase = blockIdx.x * GBN, Mbase = blockIdx.y * GBM;

    const char* Ah = (const char*)(g_zhi + (size_t)Mbase * NFFT);
    const char* Al = (const char*)(g_zlo + (size_t)Mbase * NFFT);
    const char* Bw = (const char*)(g_w16 + (size_t)Nbase * NFFT);

    float acc[4][4][4];
#pragma unroll
    for (int i = 0; i < 4; i++)
#pragma unroll
        for (int j = 0; j < 4; j++)
#pragma unroll
            for (int q = 0; q < 4; q++) acc[i][j][q] = 0.f;

    // per-lane ldmatrix address components
    const int a_row = warp_m * 64 + (lid & 7) + ((lid >> 3) & 1) * 8;  // + mi*16
    const int a_col = ((lid >> 4) & 1) * 16;                            // + ks*32
    const int b_row = warp_n * 32 + ((lid >> 4) & 1) * 8 + (lid & 7);   // + ng*16
    const int b_col = ((lid >> 3) & 1) * 16;                            // + ks*32

    load_chunk(sb, Ah, Al, Bw, 0, tid);
    CP_COMMIT();
    load_chunk(sb + ST_STRIDE, Ah, Al, Bw, GBK, tid);
    CP_COMMIT();

    const int NIT = NFFT / GBK;  // 250
    int st_cur = 0, st_pre = 2;  // stage indices (mod 3)
    for (int it = 0; it < NIT; ++it) {
        if (it + 2 < NIT)
            load_chunk(sb + st_pre * ST_STRIDE, Ah, Al, Bw, (it + 2) * GBK, tid);
        CP_COMMIT();              // uniform group count (empty at tail)
        CP_WAIT2();
        __syncthreads();

        const uint32_t ab = sb + st_cur * ST_STRIDE;
#pragma unroll
        for (int ks = 0; ks < 4; ks++) {
            uint32_t ah[4][4], al[4][4], bw[2][4];
#pragma unroll
            for (int mi = 0; mi < 4; mi++) {
                uint32_t ad = ab + (a_row + mi * 16) * LDA + ks * 32 + a_col;
                ldmx4(ah[mi], ad);
                ldmx4(al[mi], ad + OFF_ALO);
            }
#pragma unroll
            for (int ng = 0; ng < 2; ng++) {
                uint32_t bd = ab + OFF_B + (b_row + ng * 16) * LDA + ks * 32 + b_col;
                ldmx4(bw[ng], bd);
            }
#pragma unroll
            for (int mi = 0; mi < 4; mi++)
#pragma unroll
                for (int ng = 0; ng < 2; ng++)
#pragma unroll
                    for (int h = 0; h < 2; h++) {
                        float* d = acc[mi][ng * 2 + h];
                        mma_fp16(d, ah[mi], &bw[ng][h * 2]);   // hi * W
                        mma_fp16(d, al[mi], &bw[ng][h * 2]);   // lo * W
                    }
        }
        __syncthreads();
        st_cur = (st_cur == 2) ? 0 : st_cur + 1;
        st_pre = (st_pre == 2) ? 0 : st_pre + 1;
    }

    // epilogue: bias + relu, fp32 stores
    const int r = lid >> 2, cq = (lid & 3) * 2;
#pragma unroll
    for (int mi = 0; mi < 4; mi++) {
        int m0 = Mbase + warp_m * 64 + mi * 16 + r;
#pragma unroll
        for (int nt = 0; nt < 4; nt++) {
            int n = Nbase + warp_n * 32 + nt * 8 + cq;
            if (n < OUTN) {
                float b0 = __ldg(bias + n), b1 = __ldg(bias + n + 1);
                float2 v0 = make_float2(fmaxf(acc[mi][nt][0] + b0, 0.f),
                                        fmaxf(acc[mi][nt][1] + b1, 0.f));
                float2 v1 = make_float2(fmaxf(acc[mi][nt][2] + b0, 0.f),
                                        fmaxf(acc[mi][nt][3] + b1, 0.f));
                *(float2*)(out + (size_t)m0 * OUTN + n) = v0;
                *(float2*)(out + (size_t)(m0 + 8) * OUTN + n) = v1;
            }
        }
    }
}

// ---------------------------------------------------------------------------
extern "C" void kernel_launch(void* const* d_in, const int* in_sizes, int n_in,
                              void* d_out, int out_size)
{
    const float* x0 = (const float*)d_in[0];
    const float* x1 = (const float*)d_in[1];
    const int* h0 = (const int*)d_in[2];
    const int* h1 = (const int*)d_in[3];
    const int* s0 = (const int*)d_in[4];
    const int* s1 = (const int*)d_in[5];
    const float* W = (const float*)d_in[6];
    const float* bias = (const float*)d_in[7];
    float* out = (float*)d_out;

    twinit_kernel<<<(NFFT + 255) / 256, 256>>>();
    wconv_kernel<<<OUTP, 256>>>(W);

    cudaFuncSetAttribute(fftconv_kernel,
                         cudaFuncAttributeMaxDynamicSharedMemorySize, NFFT * 8);
    fftconv_kernel<<<BATCH, TPB, NFFT * 8>>>(x0, x1, h0, h1, s0, s1);

    cudaFuncSetAttribute(gemm_mma_kernel,
                         cudaFuncAttributeMaxDynamicSharedMemorySize, GSMEM_TOTAL);
    gemm_mma_kernel<<<dim3(OUTP / GBN, BATCH / GBM), GT, GSMEM_TOTAL>>>(bias, out);
}

// round 14
// speedup vs baseline: 1.4051x; 1.0005x over previous
#include <cuda_runtime.h>
#include <cuda_fp16.h>
#include <math.h>
#include <stdint.h>

#define NFFT  16000
#define DIN   2048
#define BATCH 1024
#define OUTN  3000
#define OUTP  3072
#define TPB   512

// ---------------- device globals (no runtime allocation) ----------------
__device__ float2 g_tw[NFFT];                      // W_16000^t = (cos, -sin)
__device__ __half g_zhi[BATCH * (size_t)NFFT];
__device__ __half g_zlo[BATCH * (size_t)NFFT];
__device__ __half g_w16[OUTP * (size_t)NFFT];

// ---------------- helpers ----------------
__device__ __forceinline__ uint32_t smem_u32(const void* p) {
    uint32_t a;
    asm("{ .reg .u64 t; cvta.to.shared.u64 t, %1; cvt.u32.u64 %0, t; }" : "=r"(a) : "l"(p));
    return a;
}
__device__ __forceinline__ int rev7(int x) { return (int)(__brev((unsigned)x) >> 25); }
__device__ __forceinline__ int rev5(int n) {
    int d0 = n % 5; n /= 5; int d1 = n % 5; int d2 = n / 5;
    return d0 * 25 + d1 * 5 + d2;
}
__device__ __forceinline__ float2 cmul(float2 a, float2 b) {
    return make_float2(a.x * b.x - a.y * b.y, a.x * b.y + a.y * b.x);
}
__device__ __forceinline__ float2 cmulc(float2 a, float2 b) {  // a * conj(b)
    return make_float2(a.x * b.x + a.y * b.y, a.y * b.x - a.x * b.y);
}
__device__ __forceinline__ float2 cadd(float2 a, float2 b) { return make_float2(a.x + b.x, a.y + b.y); }
__device__ __forceinline__ float2 csub(float2 a, float2 b) { return make_float2(a.x - b.x, a.y - b.y); }

// ---------------- portable tensor-core / async-copy PTX (sm_80+) ----------------
#define CP_ASYNC16(dst, src) \
    asm volatile("cp.async.cg.shared.global [%0], [%1], 16;" :: "r"(dst), "l"(src))
#define CP_COMMIT() asm volatile("cp.async.commit_group;" ::: "memory")
#define CP_WAIT2()  asm volatile("cp.async.wait_group 2;" ::: "memory")

__device__ __forceinline__ void ldmx4(uint32_t* r, uint32_t addr) {
    asm volatile("ldmatrix.sync.aligned.m8n8.x4.shared.b16 {%0,%1,%2,%3}, [%4];"
        : "=r"(r[0]), "=r"(r[1]), "=r"(r[2]), "=r"(r[3]) : "r"(addr));
}
__device__ __forceinline__ void mma_fp16(float* d, const uint32_t* a, const uint32_t* b) {
    asm volatile(
        "mma.sync.aligned.m16n8k16.row.col.f32.f16.f16.f32 "
        "{%0,%1,%2,%3}, {%4,%5,%6,%7}, {%8,%9}, {%0,%1,%2,%3};"
        : "+f"(d[0]), "+f"(d[1]), "+f"(d[2]), "+f"(d[3])
        : "r"(a[0]), "r"(a[1]), "r"(a[2]), "r"(a[3]), "r"(b[0]), "r"(b[1]));
}

// ---------------------------------------------------------------------------
// twiddle table init: g_tw[t] = exp(-2 pi i t / 16000)
// ---------------------------------------------------------------------------
__global__ void twinit_kernel() {
    int t = blockIdx.x * blockDim.x + threadIdx.x;
    if (t < NFFT) {
        double s, c;
        sincospi(-(double)t / 8000.0, &s, &c);
        g_tw[t] = make_float2((float)c, (float)s);
    }
}

// ---------------------------------------------------------------------------
// W -> fp16, padded to OUTP rows (pad rows = 0)
// ---------------------------------------------------------------------------
__global__ void wconv_kernel(const float* __restrict__ W) {
    int row = blockIdx.x;
    const float4* src = (const float4*)(W + (size_t)row * NFFT);
    uint2* dst = (uint2*)(g_w16 + (size_t)row * NFFT);
    bool ok = row < OUTN;
    for (int c4 = threadIdx.x; c4 < NFFT / 4; c4 += blockDim.x) {
        float4 v = ok ? __ldg(src + c4) : make_float4(0.f, 0.f, 0.f, 0.f);
        __half2 lo2 = __floats2half2_rn(v.x, v.y);
        __half2 hi2 = __floats2half2_rn(v.z, v.w);
        uint2 p;
        p.x = *(const uint32_t*)&lo2;
        p.y = *(const uint32_t*)&hi2;
        dst[c4] = p;
    }
}

// ---------------------------------------------------------------------------
// Fused count-sketch + forward FFT(p0 + i p1) + pointwise product + inverse
// FFT. Radix-2 stages fused in register pairs; mid twiddles folded into
// adjacent radix-2 sweeps. One block per batch row. Output: z as fp16 hi/lo.
// ---------------------------------------------------------------------------

// forward DIT fused pair: stage len=L then len=2L (butterflies over n2, stride 125)
__device__ __forceinline__ void fwd_r2_pair(float2* sh, int tid, int L) {
    const int H = L >> 1, s1 = NFFT / L, s2 = (NFFT / 2) / L;
    for (int t = tid; t < 4000; t += TPB) {
        int col = t % 125, q = t / 125;
        int g = q / H, p = q - g * H;
        int base = col + 125 * (g * 2 * L + p);
        float2 v0 = sh[base];
        float2 v1 = sh[base + 125 * H];
        float2 v2 = sh[base + 125 * L];
        float2 v3 = sh[base + 125 * (L + H)];
        float2 w1 = __ldg(&g_tw[p * s1]);
        float2 t1 = cmul(w1, v1), t3 = cmul(w1, v3);
        float2 x0 = cadd(v0, t1), x1 = csub(v0, t1);
        float2 x2 = cadd(v2, t3), x3 = csub(v2, t3);
        float2 w2 = __ldg(&g_tw[p * s2]);
        float2 w2b = __ldg(&g_tw[(p + H) * s2]);
        float2 u2 = cmul(w2, x2), u3 = cmul(w2b, x3);
        sh[base]                 = cadd(x0, u2);
        sh[base + 125 * H]       = cadd(x1, u3);
        sh[base + 125 * L]       = csub(x0, u2);
        sh[base + 125 * (L + H)] = csub(x1, u3);
    }
    __syncthreads();
}

// inverse DIF fused pair: stage len=2L then len=L. midfold: multiply inputs
// by conj(tw[n1*k2]) (only for the first pair, 2L = 128).
__device__ __forceinline__ void inv_r2_pair(float2* sh, int tid, int L, bool midfold) {
    const int H = L >> 1, s1 = NFFT / L, s2 = (NFFT / 2) / L;
    for (int t = tid; t < 4000; t += TPB) {
        int col = t % 125, q = t / 125;
        int g = q / H, p = q - g * H;
        int base = col + 125 * (g * 2 * L + p);
        float2 v0 = sh[base];
        float2 v1 = sh[base + 125 * H];
        float2 v2 = sh[base + 125 * L];
        float2 v3 = sh[base + 125 * (L + H)];
        if (midfold) {  // 2L == 128: g == 0, positions p, p+H, p+L, p+L+H
            int n1 = rev5(col);
            v0 = cmulc(v0, __ldg(&g_tw[n1 * p]));
            v1 = cmulc(v1, __ldg(&g_tw[n1 * (p + H)]));
            v2 = cmulc(v2, __ldg(&g_tw[n1 * (p + L)]));
            v3 = cmulc(v3, __ldg(&g_tw[n1 * (p + L + H)]));
        }
        float2 w2a = __ldg(&g_tw[p * s2]);
        float2 w2b = __ldg(&g_tw[(p + H) * s2]);
        float2 y0 = cadd(v0, v2), y2 = cmulc(csub(v0, v2), w2a);
        float2 y1 = cadd(v1, v3), y3 = cmulc(csub(v1, v3), w2b);
        float2 w1 = __ldg(&g_tw[p * s1]);
        sh[base]                 = cadd(y0, y1);
        sh[base + 125 * H]       = cmulc(csub(y0, y1), w1);
        sh[base + 125 * L]       = cadd(y2, y3);
        sh[base + 125 * (L + H)] = cmulc(csub(y2, y3), w1);
    }
    __syncthreads();
}

__global__ void __launch_bounds__(TPB, 1) fftconv_kernel(
    const float* __restrict__ x0, const float* __restrict__ x1,
    const int* __restrict__ h0, const int* __restrict__ h1,
    const int* __restrict__ s0, const int* __restrict__ s1)
{
    extern __shared__ float2 sh[];  // 16000 complex = 128000 B
    const int b = blockIdx.x, tid = threadIdx.x;

    for (int i = tid; i < NFFT; i += TPB) sh[i] = make_float2(0.f, 0.f);
    __syncthreads();

    // scatter count sketches (p0 -> re, p1 -> im), pre-permuted addresses
    for (int i = tid; i < DIN; i += TPB) {
        int bin = h0[i];
        float v = x0[b * DIN + i] * (float)(2 * s0[i] - 1);
        int addr = rev5(bin % 125) + 125 * rev7(bin / 125);
        atomicAdd(&sh[addr].x, v);
        bin = h1[i];
        v = x1[b * DIN + i] * (float)(2 * s1[i] - 1);
        addr = rev5(bin % 125) + 125 * rev7(bin / 125);
        atomicAdd(&sh[addr].y, v);
    }
    __syncthreads();

    // ---- forward radix-2 DIT: fused (2,4), (8,16), (32,64) ----
    fwd_r2_pair(sh, tid, 2);
    fwd_r2_pair(sh, tid, 8);
    fwd_r2_pair(sh, tid, 32);

    // ---- forward single stage len=128 with mid-twiddle fold ----
    for (int t = tid; t < 8000; t += TPB) {
        int col = t % 125, pos = t / 125;
        int ia = col + 125 * pos, ib = ia + 125 * 64;
        float2 w = __ldg(&g_tw[pos * 125]);
        float2 A = sh[ia], B = sh[ib];
        float2 tb = cmul(w, B);
        float2 o0 = cadd(A, tb), o1 = csub(A, tb);
        int n1 = rev5(col);
        sh[ia] = cmul(o0, __ldg(&g_tw[n1 * pos]));
        sh[ib] = cmul(o1, __ldg(&g_tw[n1 * (pos + 64)]));
    }
    __syncthreads();

    const float W5c[5]  = {1.f, 0.30901699f, -0.80901699f, -0.80901699f, 0.30901699f};
    const float W5sF[5] = {0.f, -0.95105652f, -0.58778525f, 0.58778525f, 0.95105652f};
    const float W5sI[5] = {0.f,  0.95105652f,  0.58778525f, -0.58778525f, -0.95105652f};

    // ---- forward radix-5 DIT over n1 (stride 1) ----
    for (int len = 5; len <= 125; len *= 5) {
        int span = len / 5, step = NFFT / len;
        for (int t = tid; t < 3200; t += TPB) {
            int k2 = t & 127, bf = t >> 7;
            int g = bf / span, pos = bf - g * span;
            int base = 125 * k2 + g * len + pos;
            float2 a[5];
#pragma unroll
            for (int q = 0; q < 5; q++) a[q] = sh[base + q * span];
#pragma unroll
            for (int t5 = 1; t5 < 5; t5++) {
                float2 w = __ldg(&g_tw[pos * t5 * step]);
                a[t5] = cmul(a[t5], w);
            }
#pragma unroll
            for (int q = 0; q < 5; q++) {
                float2 o = a[0];
#pragma unroll
                for (int t5 = 1; t5 < 5; t5++) {
                    int r = (q * t5) % 5;
                    o.x += a[t5].x * W5c[r] - a[t5].y * W5sF[r];
                    o.y += a[t5].x * W5sF[r] + a[t5].y * W5c[r];
                }
                sh[base + q * span] = o;
            }
        }
        __syncthreads();
    }

    // ---- pointwise: separate P0/P1, Z = P0*P1, Hermitian fill ----
    for (int k = tid; k <= 8000; k += TPB) {
        int kc = (k == 0) ? 0 : (NFFT - k);
        int sA = (k >> 7) + 125 * (k & 127);
        int sB = (kc >> 7) + 125 * (kc & 127);
        float2 FA = sh[sA], FB = sh[sB];
        float p0r = 0.5f * (FA.x + FB.x), p0i = 0.5f * (FA.y - FB.y);
        float p1r = 0.5f * (FA.y + FB.y), p1i = 0.5f * (FB.x - FA.x);
        float zr = p0r * p1r - p0i * p1i;
        float zi = p0r * p1i + p0i * p1r;
        sh[sA] = make_float2(zr, zi);
        if (sB != sA) sh[sB] = make_float2(zr, -zi);
    }
    __syncthreads();

    // ---- inverse radix-5 DIF over k1 (stride 1) ----
    for (int len = 125; len >= 5; len /= 5) {
        int span = len / 5, step = NFFT / len;
        for (int t = tid; t < 3200; t += TPB) {
            int k2 = t & 127, bf = t >> 7;
            int g = bf / span, pos = bf - g * span;
            int base = 125 * k2 + g * len + pos;
            float2 a[5];
#pragma unroll
            for (int q = 0; q < 5; q++) a[q] = sh[base + q * span];
#pragma unroll
            for (int q = 0; q < 5; q++) {
                float2 o = a[0];
#pragma unroll
                for (int t5 = 1; t5 < 5; t5++) {
                    int r = (q * t5) % 5;
                    o.x += a[t5].x * W5c[r] - a[t5].y * W5sI[r];
                    o.y += a[t5].x * W5sI[r] + a[t5].y * W5c[r];
                }
                float2 w = __ldg(&g_tw[pos * q * step]);
                w.y = -w.y;
                sh[base + q * span] = cmul(o, w);
            }
        }
        __syncthreads();
    }

    // ---- inverse radix-2 DIF: fused (128,64) w/ mid fold, (32,16), (8,4) ----
    inv_r2_pair(sh, tid, 64, true);
    inv_r2_pair(sh, tid, 16, false);
    inv_r2_pair(sh, tid, 4, false);

    // ---- inverse single stage len=2 (twiddle = 1) ----
    for (int t = tid; t < 8000; t += TPB) {
        int col = t % 125, bfi = t / 125;
        int ia = col + 125 * (2 * bfi), ib = ia + 125;
        float2 A = sh[ia], B = sh[ib];
        sh[ia] = cadd(A, B);
        sh[ib] = csub(A, B);
    }
    __syncthreads();

    // ---- store z as fp16 hi/lo, unpermute, scale 1/N ----
    for (int n = tid; n < NFFT; n += TPB) {
        int addr = rev5(n % 125) + 125 * rev7(n / 125);
        float zr = sh[addr].x * (1.f / 16000.f);
        __half hb = __float2half_rn(zr);
        g_zhi[b * (size_t)NFFT + n] = hb;
        g_zlo[b * (size_t)NFFT + n] = __float2half_rn(zr - __half2float(hb));
    }
}

// ---------------------------------------------------------------------------
// GEMM via mma.sync (HMMA fp16): out = relu(z @ W^T + b)
// fp16 split-A 2-pass (zhi*W + zlo*W), fp32 accumulate. Two-sweep MMA
// issue order: all hi-pass MMAs (16 independent accumulators), then all
// lo-pass MMAs — breaks accumulator RAW back-to-back dependency.
// CTA tile 128x192, K-chunk 64, 3-stage cp.async pipeline, 12 warps.
// ---------------------------------------------------------------------------
#define GBM 128
#define GBN 192
#define GBK 64
#define GT  384
#define LDA 144                       // smem row pitch bytes (64 fp16 + 8 pad)
#define A_TILE (GBM * LDA)            // 18432
#define B_TILE (GBN * LDA)            // 27648
#define OFF_ALO  A_TILE
#define OFF_B    (2 * A_TILE)
#define ST_STRIDE (2 * A_TILE + B_TILE)       // 64512
#define GSMEM_TOTAL (3 * ST_STRIDE)           // 193536

__device__ __forceinline__ void load_chunk(
    uint32_t sbase, const char* Ah, const char* Al, const char* Bw,
    int kb, int tid)
{
#pragma unroll
    for (int j = 0; j < 3; j++) {           // A: 128 rows x 8 units (1024)
        int u = tid + j * GT;
        if (u < GBM * 8) {
            int row = u >> 3, c = u & 7;
            size_t g = ((size_t)row * NFFT + kb + c * 8) * 2;
            uint32_t so = sbase + row * LDA + c * 16;
            CP_ASYNC16(so, Ah + g);
            CP_ASYNC16(so + OFF_ALO, Al + g);
        }
    }
#pragma unroll
    for (int j = 0; j < 4; j++) {           // B: 192 rows x 8 units (1536)
        int u = tid + j * GT;
        int row = u >> 3, c = u & 7;
        size_t g = ((size_t)row * NFFT + kb + c * 8) * 2;
        uint32_t so = sbase + OFF_B + row * LDA + c * 16;
        CP_ASYNC16(so, Bw + g);
    }
}

__global__ void __launch_bounds__(GT, 1) gemm_mma_kernel(
    const float* __restrict__ bias, float* __restrict__ out)
{
    extern __shared__ char smem[];
    const uint32_t sb = smem_u32(smem);
    const int tid = threadIdx.x, wid = tid >> 5, lid = tid & 31;
    const int warp_m = wid & 1, warp_n = wid >> 1;   // 2 x 6 warps
    const int Nbase = blockIdx.x * GBN, Mbase = blockIdx.y * GBM;

    const char* Ah = (const char*)(g_zhi + (size_t)Mbase * NFFT);
    const char* Al = (const char*)(g_zlo + (size_t)Mbase * NFFT);
    const char* Bw = (const char*)(g_w16 + (size_t)Nbase * NFFT);

    float acc[4][4][4];
#pragma unroll
    for (int i = 0; i < 4; i++)
#pragma unroll
        for (int j = 0; j < 4; j++)
#pragma unroll
            for (int q = 0; q < 4; q++) acc[i][j][q] = 0.f;

    // per-lane ldmatrix address components
    const int a_row = warp_m * 64 + (lid & 7) + ((lid >> 3) & 1) * 8;  // + mi*16
    const int a_col = ((lid >> 4) & 1) * 16;                            // + ks*32
    const int b_row = warp_n * 32 + ((lid >> 4) & 1) * 8 + (lid & 7);   // + ng*16
    const int b_col = ((lid >> 3) & 1) * 16;                            // + ks*32

    load_chunk(sb, Ah, Al, Bw, 0, tid);
    CP_COMMIT();
    load_chunk(sb + ST_STRIDE, Ah, Al, Bw, GBK, tid);
    CP_COMMIT();

    const int NIT = NFFT / GBK;  // 250
    int st_cur = 0, st_pre = 2;  // stage indices (mod 3)
    for (int it = 0; it < NIT; ++it) {
        if (it + 2 < NIT)
            load_chunk(sb + st_pre * ST_STRIDE, Ah, Al, Bw, (it + 2) * GBK, tid);
        CP_COMMIT();              // uniform group count (empty at tail)
        CP_WAIT2();
        __syncthreads();

        const uint32_t ab = sb + st_cur * ST_STRIDE;
#pragma unroll
        for (int ks = 0; ks < 4; ks++) {
            uint32_t ah[4][4], al[4][4], bw[2][4];
#pragma unroll
            for (int mi = 0; mi < 4; mi++) {
                uint32_t ad = ab + (a_row + mi * 16) * LDA + ks * 32 + a_col;
                ldmx4(ah[mi], ad);
                ldmx4(al[mi], ad + OFF_ALO);
            }
#pragma unroll
            for (int ng = 0; ng < 2; ng++) {
                uint32_t bd = ab + OFF_B + (b_row + ng * 16) * LDA + ks * 32 + b_col;
                ldmx4(bw[ng], bd);
            }
            // sweep 1: hi pass — 16 independent accumulators, no RAW chains
#pragma unroll
            for (int mi = 0; mi < 4; mi++)
#pragma unroll
                for (int ng = 0; ng < 2; ng++)
#pragma unroll
                    for (int h = 0; h < 2; h++)
                        mma_fp16(acc[mi][ng * 2 + h], ah[mi], &bw[ng][h * 2]);
            // sweep 2: lo pass — each acc reuse separated by 16 MMAs
#pragma unroll
            for (int mi = 0; mi < 4; mi++)
#pragma unroll
                for (int ng = 0; ng < 2; ng++)
#pragma unroll
                    for (int h = 0; h < 2; h++)
                        mma_fp16(acc[mi][ng * 2 + h], al[mi], &bw[ng][h * 2]);
        }
        __syncthreads();
        st_cur = (st_cur == 2) ? 0 : st_cur + 1;
        st_pre = (st_pre == 2) ? 0 : st_pre + 1;
    }

    // epilogue: bias + relu, fp32 stores
    const int r = lid >> 2, cq = (lid & 3) * 2;
#pragma unroll
    for (int mi = 0; mi < 4; mi++) {
        int m0 = Mbase + warp_m * 64 + mi * 16 + r;
#pragma unroll
        for (int nt = 0; nt < 4; nt++) {
            int n = Nbase + warp_n * 32 + nt * 8 + cq;
            if (n < OUTN) {
                float b0 = __ldg(bias + n), b1 = __ldg(bias + n + 1);
                float2 v0 = make_float2(fmaxf(acc[mi][nt][0] + b0, 0.f),
                                        fmaxf(acc[mi][nt][1] + b1, 0.f));
                float2 v1 = make_float2(fmaxf(acc[mi][nt][2] + b0, 0.f),
                                        fmaxf(acc[mi][nt][3] + b1, 0.f));
                *(float2*)(out + (size_t)m0 * OUTN + n) = v0;
                *(float2*)(out + (size_t)(m0 + 8) * OUTN + n) = v1;
            }
        }
    }
}

// ---------------------------------------------------------------------------
extern "C" void kernel_launch(void* const* d_in, const int* in_sizes, int n_in,
                              void* d_out, int out_size)
{
    const float* x0 = (const float*)d_in[0];
    const float* x1 = (const float*)d_in[1];
    const int* h0 = (const int*)d_in[2];
    const int* h1 = (const int*)d_in[3];
    const int* s0 = (const int*)d_in[4];
    const int* s1 = (const int*)d_in[5];
    const float* W = (const float*)d_in[6];
    const float* bias = (const float*)d_in[7];
    float* out = (float*)d_out;

    twinit_kernel<<<(NFFT + 255) / 256, 256>>>();
    wconv_kernel<<<OUTP, 256>>>(W);

    cudaFuncSetAttribute(fftconv_kernel,
                         cudaFuncAttributeMaxDynamicSharedMemorySize, NFFT * 8);
    fftconv_kernel<<<BATCH, TPB, NFFT * 8>>>(x0, x1, h0, h1, s0, s1);

    cudaFuncSetAttribute(gemm_mma_kernel,
                         cudaFuncAttributeMaxDynamicSharedMemorySize, GSMEM_TOTAL);
    gemm_mma_kernel<<<dim3(OUTP / GBN, BATCH / GBM), GT, GSMEM_TOTAL>>>(bias, out);
}

// round 15
// speedup vs baseline: 1.4104x; 1.0038x over previous
#include <cuda_runtime.h>
#include <cuda_fp16.h>
#include <math.h>
#include <stdint.h>

#define NFFT  16000
#define DIN   2048
#define BATCH 1024
#define OUTN  3000
#define OUTP  3072
#define TPB   512

// ---------------- device globals (no runtime allocation) ----------------
__device__ float2 g_tw[NFFT];                      // W_16000^t = (cos, -sin)
__device__ __half g_zhi[BATCH * (size_t)NFFT];
__device__ __half g_zlo[BATCH * (size_t)NFFT];
__device__ __half g_w16[OUTP * (size_t)NFFT];

// ---------------- helpers ----------------
__device__ __forceinline__ uint32_t smem_u32(const void* p) {
    uint32_t a;
    asm("{ .reg .u64 t; cvta.to.shared.u64 t, %1; cvt.u32.u64 %0, t; }" : "=r"(a) : "l"(p));
    return a;
}
__device__ __forceinline__ int rev7(int x) { return (int)(__brev((unsigned)x) >> 25); }
__device__ __forceinline__ int rev5(int n) {
    int d0 = n % 5; n /= 5; int d1 = n % 5; int d2 = n / 5;
    return d0 * 25 + d1 * 5 + d2;
}
__device__ __forceinline__ float2 cmul(float2 a, float2 b) {
    return make_float2(a.x * b.x - a.y * b.y, a.x * b.y + a.y * b.x);
}
__device__ __forceinline__ float2 cmulc(float2 a, float2 b) {  // a * conj(b)
    return make_float2(a.x * b.x + a.y * b.y, a.y * b.x - a.x * b.y);
}
__device__ __forceinline__ float2 cadd(float2 a, float2 b) { return make_float2(a.x + b.x, a.y + b.y); }
__device__ __forceinline__ float2 csub(float2 a, float2 b) { return make_float2(a.x - b.x, a.y - b.y); }

// ---------------- portable tensor-core / async-copy PTX (sm_80+) ----------------
#define CP_ASYNC16(dst, src) \
    asm volatile("cp.async.cg.shared.global [%0], [%1], 16;" :: "r"(dst), "l"(src))
#define CP_COMMIT() asm volatile("cp.async.commit_group;" ::: "memory")
#define CP_WAIT2()  asm volatile("cp.async.wait_group 2;" ::: "memory")

__device__ __forceinline__ void ldmx4(uint32_t* r, uint32_t addr) {
    asm volatile("ldmatrix.sync.aligned.m8n8.x4.shared.b16 {%0,%1,%2,%3}, [%4];"
        : "=r"(r[0]), "=r"(r[1]), "=r"(r[2]), "=r"(r[3]) : "r"(addr));
}
__device__ __forceinline__ void mma_fp16(float* d, const uint32_t* a, const uint32_t* b) {
    asm volatile(
        "mma.sync.aligned.m16n8k16.row.col.f32.f16.f16.f32 "
        "{%0,%1,%2,%3}, {%4,%5,%6,%7}, {%8,%9}, {%0,%1,%2,%3};"
        : "+f"(d[0]), "+f"(d[1]), "+f"(d[2]), "+f"(d[3])
        : "r"(a[0]), "r"(a[1]), "r"(a[2]), "r"(a[3]), "r"(b[0]), "r"(b[1]));
}

// ---------------------------------------------------------------------------
// twiddle table init: g_tw[t] = exp(-2 pi i t / 16000)
// ---------------------------------------------------------------------------
__global__ void twinit_kernel() {
    int t = blockIdx.x * blockDim.x + threadIdx.x;
    if (t < NFFT) {
        double s, c;
        sincospi(-(double)t / 8000.0, &s, &c);
        g_tw[t] = make_float2((float)c, (float)s);
    }
}

// ---------------------------------------------------------------------------
// W -> fp16, padded to OUTP rows (pad rows = 0)
// ---------------------------------------------------------------------------
__global__ void wconv_kernel(const float* __restrict__ W) {
    int row = blockIdx.x;
    const float4* src = (const float4*)(W + (size_t)row * NFFT);
    uint2* dst = (uint2*)(g_w16 + (size_t)row * NFFT);
    bool ok = row < OUTN;
    for (int c4 = threadIdx.x; c4 < NFFT / 4; c4 += blockDim.x) {
        float4 v = ok ? __ldg(src + c4) : make_float4(0.f, 0.f, 0.f, 0.f);
        __half2 lo2 = __floats2half2_rn(v.x, v.y);
        __half2 hi2 = __floats2half2_rn(v.z, v.w);
        uint2 p;
        p.x = *(const uint32_t*)&lo2;
        p.y = *(const uint32_t*)&hi2;
        dst[c4] = p;
    }
}

// ---------------------------------------------------------------------------
// Fused count-sketch + forward FFT(p0 + i p1) + pointwise product + inverse
// FFT. Radix-2 stages fused in register pairs; mid twiddles folded into
// adjacent radix-2 sweeps. One block per batch row. Output: z as fp16 hi/lo.
// ---------------------------------------------------------------------------

// forward DIT fused pair: stage len=L then len=2L (butterflies over n2, stride 125)
__device__ __forceinline__ void fwd_r2_pair(float2* sh, int tid, int L) {
    const int H = L >> 1, s1 = NFFT / L, s2 = (NFFT / 2) / L;
    for (int t = tid; t < 4000; t += TPB) {
        int col = t % 125, q = t / 125;
        int g = q / H, p = q - g * H;
        int base = col + 125 * (g * 2 * L + p);
        float2 v0 = sh[base];
        float2 v1 = sh[base + 125 * H];
        float2 v2 = sh[base + 125 * L];
        float2 v3 = sh[base + 125 * (L + H)];
        float2 w1 = __ldg(&g_tw[p * s1]);
        float2 t1 = cmul(w1, v1), t3 = cmul(w1, v3);
        float2 x0 = cadd(v0, t1), x1 = csub(v0, t1);
        float2 x2 = cadd(v2, t3), x3 = csub(v2, t3);
        float2 w2 = __ldg(&g_tw[p * s2]);
        float2 w2b = __ldg(&g_tw[(p + H) * s2]);
        float2 u2 = cmul(w2, x2), u3 = cmul(w2b, x3);
        sh[base]                 = cadd(x0, u2);
        sh[base + 125 * H]       = cadd(x1, u3);
        sh[base + 125 * L]       = csub(x0, u2);
        sh[base + 125 * (L + H)] = csub(x1, u3);
    }
    __syncthreads();
}

// inverse DIF fused pair: stage len=2L then len=L. midfold: multiply inputs
// by conj(tw[n1*k2]) (only for the first pair, 2L = 128).
__device__ __forceinline__ void inv_r2_pair(float2* sh, int tid, int L, bool midfold) {
    const int H = L >> 1, s1 = NFFT / L, s2 = (NFFT / 2) / L;
    for (int t = tid; t < 4000; t += TPB) {
        int col = t % 125, q = t / 125;
        int g = q / H, p = q - g * H;
        int base = col + 125 * (g * 2 * L + p);
        float2 v0 = sh[base];
        float2 v1 = sh[base + 125 * H];
        float2 v2 = sh[base + 125 * L];
        float2 v3 = sh[base + 125 * (L + H)];
        if (midfold) {  // 2L == 128: g == 0, positions p, p+H, p+L, p+L+H
            int n1 = rev5(col);
            v0 = cmulc(v0, __ldg(&g_tw[n1 * p]));
            v1 = cmulc(v1, __ldg(&g_tw[n1 * (p + H)]));
            v2 = cmulc(v2, __ldg(&g_tw[n1 * (p + L)]));
            v3 = cmulc(v3, __ldg(&g_tw[n1 * (p + L + H)]));
        }
        float2 w2a = __ldg(&g_tw[p * s2]);
        float2 w2b = __ldg(&g_tw[(p + H) * s2]);
        float2 y0 = cadd(v0, v2), y2 = cmulc(csub(v0, v2), w2a);
        float2 y1 = cadd(v1, v3), y3 = cmulc(csub(v1, v3), w2b);
        float2 w1 = __ldg(&g_tw[p * s1]);
        sh[base]                 = cadd(y0, y1);
        sh[base + 125 * H]       = cmulc(csub(y0, y1), w1);
        sh[base + 125 * L]       = cadd(y2, y3);
        sh[base + 125 * (L + H)] = cmulc(csub(y2, y3), w1);
    }
    __syncthreads();
}

__global__ void __launch_bounds__(TPB, 1) fftconv_kernel(
    const float* __restrict__ x0, const float* __restrict__ x1,
    const int* __restrict__ h0, const int* __restrict__ h1,
    const int* __restrict__ s0, const int* __restrict__ s1)
{
    extern __shared__ float2 sh[];  // 16000 complex = 128000 B
    const int b = blockIdx.x, tid = threadIdx.x;

    for (int i = tid; i < NFFT; i += TPB) sh[i] = make_float2(0.f, 0.f);
    __syncthreads();

    // scatter count sketches (p0 -> re, p1 -> im), pre-permuted addresses
    for (int i = tid; i < DIN; i += TPB) {
        int bin = h0[i];
        float v = x0[b * DIN + i] * (float)(2 * s0[i] - 1);
        int addr = rev5(bin % 125) + 125 * rev7(bin / 125);
        atomicAdd(&sh[addr].x, v);
        bin = h1[i];
        v = x1[b * DIN + i] * (float)(2 * s1[i] - 1);
        addr = rev5(bin % 125) + 125 * rev7(bin / 125);
        atomicAdd(&sh[addr].y, v);
    }
    __syncthreads();

    // ---- forward radix-2 DIT: fused (2,4), (8,16), (32,64) ----
    fwd_r2_pair(sh, tid, 2);
    fwd_r2_pair(sh, tid, 8);
    fwd_r2_pair(sh, tid, 32);

    // ---- forward single stage len=128 with mid-twiddle fold ----
    for (int t = tid; t < 8000; t += TPB) {
        int col = t % 125, pos = t / 125;
        int ia = col + 125 * pos, ib = ia + 125 * 64;
        float2 w = __ldg(&g_tw[pos * 125]);
        float2 A = sh[ia], B = sh[ib];
        float2 tb = cmul(w, B);
        float2 o0 = cadd(A, tb), o1 = csub(A, tb);
        int n1 = rev5(col);
        sh[ia] = cmul(o0, __ldg(&g_tw[n1 * pos]));
        sh[ib] = cmul(o1, __ldg(&g_tw[n1 * (pos + 64)]));
    }
    __syncthreads();

    const float W5c[5]  = {1.f, 0.30901699f, -0.80901699f, -0.80901699f, 0.30901699f};
    const float W5sF[5] = {0.f, -0.95105652f, -0.58778525f, 0.58778525f, 0.95105652f};
    const float W5sI[5] = {0.f,  0.95105652f,  0.58778525f, -0.58778525f, -0.95105652f};

    // ---- forward radix-5 DIT over n1 (stride 1) ----
    for (int len = 5; len <= 125; len *= 5) {
        int span = len / 5, step = NFFT / len;
        for (int t = tid; t < 3200; t += TPB) {
            int k2 = t & 127, bf = t >> 7;
            int g = bf / span, pos = bf - g * span;
            int base = 125 * k2 + g * len + pos;
            float2 a[5];
#pragma unroll
            for (int q = 0; q < 5; q++) a[q] = sh[base + q * span];
#pragma unroll
            for (int t5 = 1; t5 < 5; t5++) {
                float2 w = __ldg(&g_tw[pos * t5 * step]);
                a[t5] = cmul(a[t5], w);
            }
#pragma unroll
            for (int q = 0; q < 5; q++) {
                float2 o = a[0];
#pragma unroll
                for (int t5 = 1; t5 < 5; t5++) {
                    int r = (q * t5) % 5;
                    o.x += a[t5].x * W5c[r] - a[t5].y * W5sF[r];
                    o.y += a[t5].x * W5sF[r] + a[t5].y * W5c[r];
                }
                sh[base + q * span] = o;
            }
        }
        __syncthreads();
    }

    // ---- pointwise: separate P0/P1, Z = P0*P1, Hermitian fill ----
    for (int k = tid; k <= 8000; k += TPB) {
        int kc = (k == 0) ? 0 : (NFFT - k);
        int sA = (k >> 7) + 125 * (k & 127);
        int sB = (kc >> 7) + 125 * (kc & 127);
        float2 FA = sh[sA], FB = sh[sB];
        float p0r = 0.5f * (FA.x + FB.x), p0i = 0.5f * (FA.y - FB.y);
        float p1r = 0.5f * (FA.y + FB.y), p1i = 0.5f * (FB.x - FA.x);
        float zr = p0r * p1r - p0i * p1i;
        float zi = p0r * p1i + p0i * p1r;
        sh[sA] = make_float2(zr, zi);
        if (sB != sA) sh[sB] = make_float2(zr, -zi);
    }
    __syncthreads();

    // ---- inverse radix-5 DIF over k1 (stride 1) ----
    for (int len = 125; len >= 5; len /= 5) {
        int span = len / 5, step = NFFT / len;
        for (int t = tid; t < 3200; t += TPB) {
            int k2 = t & 127, bf = t >> 7;
            int g = bf / span, pos = bf - g * span;
            int base = 125 * k2 + g * len + pos;
            float2 a[5];
#pragma unroll
            for (int q = 0; q < 5; q++) a[q] = sh[base + q * span];
#pragma unroll
            for (int q = 0; q < 5; q++) {
                float2 o = a[0];
#pragma unroll
                for (int t5 = 1; t5 < 5; t5++) {
                    int r = (q * t5) % 5;
                    o.x += a[t5].x * W5c[r] - a[t5].y * W5sI[r];
                    o.y += a[t5].x * W5sI[r] + a[t5].y * W5c[r];
                }
                float2 w = __ldg(&g_tw[pos * q * step]);
                w.y = -w.y;
                sh[base + q * span] = cmul(o, w);
            }
        }
        __syncthreads();
    }

    // ---- inverse radix-2 DIF: fused (128,64) w/ mid fold, (32,16), (8,4) ----
    inv_r2_pair(sh, tid, 64, true);
    inv_r2_pair(sh, tid, 16, false);
    inv_r2_pair(sh, tid, 4, false);

    // ---- inverse single stage len=2 (twiddle = 1) ----
    for (int t = tid; t < 8000; t += TPB) {
        int col = t % 125, bfi = t / 125;
        int ia = col + 125 * (2 * bfi), ib = ia + 125;
        float2 A = sh[ia], B = sh[ib];
        sh[ia] = cadd(A, B);
        sh[ib] = csub(A, B);
    }
    __syncthreads();

    // ---- store z as fp16 hi/lo, unpermute, scale 1/N ----
    for (int n = tid; n < NFFT; n += TPB) {
        int addr = rev5(n % 125) + 125 * rev7(n / 125);
        float zr = sh[addr].x * (1.f / 16000.f);
        __half hb = __float2half_rn(zr);
        g_zhi[b * (size_t)NFFT + n] = hb;
        g_zlo[b * (size_t)NFFT + n] = __float2half_rn(zr - __half2float(hb));
    }
}

// ---------------------------------------------------------------------------
// GEMM via mma.sync (HMMA fp16): out = relu(z @ W^T + b)
// fp16 split-A 2-pass (zhi*W + zlo*W), fp32 accumulate. Two-sweep MMA
// issue order: all hi-pass MMAs (16 independent accumulators), then all
// lo-pass MMAs — breaks accumulator RAW back-to-back dependency.
// CTA tile 128x192, K-chunk 64, 3-stage cp.async pipeline, 12 warps.
// ---------------------------------------------------------------------------
#define GBM 128
#define GBN 192
#define GBK 64
#define GT  384
#define LDA 144                       // smem row pitch bytes (64 fp16 + 8 pad)
#define A_TILE (GBM * LDA)            // 18432
#define B_TILE (GBN * LDA)            // 27648
#define OFF_ALO  A_TILE
#define OFF_B    (2 * A_TILE)
#define ST_STRIDE (2 * A_TILE + B_TILE)       // 64512
#define GSMEM_TOTAL (3 * ST_STRIDE)           // 193536

__device__ __forceinline__ void load_chunk(
    uint32_t sbase, const char* Ah, const char* Al, const char* Bw,
    int kb, int tid)
{
#pragma unroll
    for (int j = 0; j < 3; j++) {           // A: 128 rows x 8 units (1024)
        int u = tid + j * GT;
        if (u < GBM * 8) {
            int row = u >> 3, c = u & 7;
            size_t g = ((size_t)row * NFFT + kb + c * 8) * 2;
            uint32_t so = sbase + row * LDA + c * 16;
            CP_ASYNC16(so, Ah + g);
            CP_ASYNC16(so + OFF_ALO, Al + g);
        }
    }
#pragma unroll
    for (int j = 0; j < 4; j++) {           // B: 192 rows x 8 units (1536)
        int u = tid + j * GT;
        int row = u >> 3, c = u & 7;
        size_t g = ((size_t)row * NFFT + kb + c * 8) * 2;
        uint32_t so = sbase + OFF_B + row * LDA + c * 16;
        CP_ASYNC16(so, Bw + g);
    }
}

__global__ void __launch_bounds__(GT, 1) gemm_mma_kernel(
    const float* __restrict__ bias, float* __restrict__ out)
{
    extern __shared__ char smem[];
    const uint32_t sb = smem_u32(smem);
    const int tid = threadIdx.x, wid = tid >> 5, lid = tid & 31;
    const int warp_m = wid & 1, warp_n = wid >> 1;   // 2 x 6 warps
    const int Nbase = blockIdx.x * GBN, Mbase = blockIdx.y * GBM;

    const char* Ah = (const char*)(g_zhi + (size_t)Mbase * NFFT);
    const char* Al = (const char*)(g_zlo + (size_t)Mbase * NFFT);
    const char* Bw = (const char*)(g_w16 + (size_t)Nbase * NFFT);

    float acc[4][4][4];
#pragma unroll
    for (int i = 0; i < 4; i++)
#pragma unroll
        for (int j = 0; j < 4; j++)
#pragma unroll
            for (int q = 0; q < 4; q++) acc[i][j][q] = 0.f;

    // per-lane ldmatrix address components
    const int a_row = warp_m * 64 + (lid & 7) + ((lid >> 3) & 1) * 8;  // + mi*16
    const int a_col = ((lid >> 4) & 1) * 16;                            // + ks*32
    const int b_row = warp_n * 32 + ((lid >> 4) & 1) * 8 + (lid & 7);   // + ng*16
    const int b_col = ((lid >> 3) & 1) * 16;                            // + ks*32

    load_chunk(sb, Ah, Al, Bw, 0, tid);
    CP_COMMIT();
    load_chunk(sb + ST_STRIDE, Ah, Al, Bw, GBK, tid);
    CP_COMMIT();

    const int NIT = NFFT / GBK;  // 250
    int st_cur = 0, st_pre = 2;  // stage indices (mod 3)
    for (int it = 0; it < NIT; ++it) {
        if (it + 2 < NIT)
            load_chunk(sb + st_pre * ST_STRIDE, Ah, Al, Bw, (it + 2) * GBK, tid);
        CP_COMMIT();              // uniform group count (empty at tail)
        CP_WAIT2();
        __syncthreads();

        const uint32_t ab = sb + st_cur * ST_STRIDE;
#pragma unroll
        for (int ks = 0; ks < 4; ks++) {
            uint32_t ah[4][4], al[4][4], bw[2][4];
#pragma unroll
            for (int mi = 0; mi < 4; mi++) {
                uint32_t ad = ab + (a_row + mi * 16) * LDA + ks * 32 + a_col;
                ldmx4(ah[mi], ad);
                ldmx4(al[mi], ad + OFF_ALO);
            }
#pragma unroll
            for (int ng = 0; ng < 2; ng++) {
                uint32_t bd = ab + OFF_B + (b_row + ng * 16) * LDA + ks * 32 + b_col;
                ldmx4(bw[ng], bd);
            }
            // sweep 1: hi pass — 16 independent accumulators, no RAW chains
#pragma unroll
            for (int mi = 0; mi < 4; mi++)
#pragma unroll
                for (int ng = 0; ng < 2; ng++)
#pragma unroll
                    for (int h = 0; h < 2; h++)
                        mma_fp16(acc[mi][ng * 2 + h], ah[mi], &bw[ng][h * 2]);
            // sweep 2: lo pass — each acc reuse separated by 16 MMAs
#pragma unroll
            for (int mi = 0; mi < 4; mi++)
#pragma unroll
                for (int ng = 0; ng < 2; ng++)
#pragma unroll
                    for (int h = 0; h < 2; h++)
                        mma_fp16(acc[mi][ng * 2 + h], al[mi], &bw[ng][h * 2]);
        }
        __syncthreads();
        st_cur = (st_cur == 2) ? 0 : st_cur + 1;
        st_pre = (st_pre == 2) ? 0 : st_pre + 1;
    }

    // epilogue: bias + relu, fp32 stores
    const int r = lid >> 2, cq = (lid & 3) * 2;
#pragma unroll
    for (int mi = 0; mi < 4; mi++) {
        int m0 = Mbase + warp_m * 64 + mi * 16 + r;
#pragma unroll
        for (int nt = 0; nt < 4; nt++) {
            int n = Nbase + warp_n * 32 + nt * 8 + cq;
            if (n < OUTN) {
                float b0 = __ldg(bias + n), b1 = __ldg(bias + n + 1);
                float2 v0 = make_float2(fmaxf(acc[mi][nt][0] + b0, 0.f),
                                        fmaxf(acc[mi][nt][1] + b1, 0.f));
                float2 v1 = make_float2(fmaxf(acc[mi][nt][2] + b0, 0.f),
                                        fmaxf(acc[mi][nt][3] + b1, 0.f));
                *(float2*)(out + (size_t)m0 * OUTN + n) = v0;
                *(float2*)(out + (size_t)(m0 + 8) * OUTN + n) = v1;
            }
        }
    }
}

// ---------------------------------------------------------------------------
extern "C" void kernel_launch(void* const* d_in, const int* in_sizes, int n_in,
                              void* d_out, int out_size)
{
    const float* x0 = (const float*)d_in[0];
    const float* x1 = (const float*)d_in[1];
    const int* h0 = (const int*)d_in[2];
    const int* h1 = (const int*)d_in[3];
    const int* s0 = (const int*)d_in[4];
    const int* s1 = (const int*)d_in[5];
    const float* W = (const float*)d_in[6];
    const float* bias = (const float*)d_in[7];
    float* out = (float*)d_out;

    twinit_kernel<<<(NFFT + 255) / 256, 256>>>();
    wconv_kernel<<<OUTP, 256>>>(W);

    cudaFuncSetAttribute(fftconv_kernel,
                         cudaFuncAttributeMaxDynamicSharedMemorySize, NFFT * 8);
    fftconv_kernel<<<BATCH, TPB, NFFT * 8>>>(x0, x1, h0, h1, s0, s1);

    cudaFuncSetAttribute(gemm_mma_kernel,
                         cudaFuncAttributeMaxDynamicSharedMemorySize, GSMEM_TOTAL);
    gemm_mma_kernel<<<dim3(OUTP / GBN, BATCH / GBM), GT, GSMEM_TOTAL>>>(bias, out);
}

// round 16
// speedup vs baseline: 1.8212x; 1.2912x over previous
#include <cuda_runtime.h>
#include <cuda_fp16.h>
#include <math.h>
#include <stdint.h>

#define NFFT  16000
#define DIN   2048
#define BATCH 1024
#define OUTN  3000
#define OUTP  3072
#define TPB   512

// ---------------- device globals (no runtime allocation) ----------------
__device__ float2 g_tw[NFFT];                      // W_16000^t = (cos, -sin)
__device__ __half g_z16[BATCH * (size_t)NFFT];
__device__ __half g_w16[OUTP * (size_t)NFFT];

// ---------------- helpers ----------------
__device__ __forceinline__ uint32_t smem_u32(const void* p) {
    uint32_t a;
    asm("{ .reg .u64 t; cvta.to.shared.u64 t, %1; cvt.u32.u64 %0, t; }" : "=r"(a) : "l"(p));
    return a;
}
__device__ __forceinline__ int rev7(int x) { return (int)(__brev((unsigned)x) >> 25); }
__device__ __forceinline__ int rev5(int n) {
    int d0 = n % 5; n /= 5; int d1 = n % 5; int d2 = n / 5;
    return d0 * 25 + d1 * 5 + d2;
}
__device__ __forceinline__ float2 cmul(float2 a, float2 b) {
    return make_float2(a.x * b.x - a.y * b.y, a.x * b.y + a.y * b.x);
}
__device__ __forceinline__ float2 cmulc(float2 a, float2 b) {  // a * conj(b)
    return make_float2(a.x * b.x + a.y * b.y, a.y * b.x - a.x * b.y);
}
__device__ __forceinline__ float2 cadd(float2 a, float2 b) { return make_float2(a.x + b.x, a.y + b.y); }
__device__ __forceinline__ float2 csub(float2 a, float2 b) { return make_float2(a.x - b.x, a.y - b.y); }

// ---------------- portable tensor-core / async-copy PTX (sm_80+) ----------------
#define CP_ASYNC16(dst, src) \
    asm volatile("cp.async.cg.shared.global [%0], [%1], 16;" :: "r"(dst), "l"(src))
#define CP_COMMIT() asm volatile("cp.async.commit_group;" ::: "memory")
#define CP_WAIT2()  asm volatile("cp.async.wait_group 2;" ::: "memory")

__device__ __forceinline__ void ldmx4(uint32_t* r, uint32_t addr) {
    asm volatile("ldmatrix.sync.aligned.m8n8.x4.shared.b16 {%0,%1,%2,%3}, [%4];"
        : "=r"(r[0]), "=r"(r[1]), "=r"(r[2]), "=r"(r[3]) : "r"(addr));
}
__device__ __forceinline__ void mma_fp16(float* d, const uint32_t* a, const uint32_t* b) {
    asm volatile(
        "mma.sync.aligned.m16n8k16.row.col.f32.f16.f16.f32 "
        "{%0,%1,%2,%3}, {%4,%5,%6,%7}, {%8,%9}, {%0,%1,%2,%3};"
        : "+f"(d[0]), "+f"(d[1]), "+f"(d[2]), "+f"(d[3])
        : "r"(a[0]), "r"(a[1]), "r"(a[2]), "r"(a[3]), "r"(b[0]), "r"(b[1]));
}

// ---------------------------------------------------------------------------
// twiddle table init: g_tw[t] = exp(-2 pi i t / 16000)
// ---------------------------------------------------------------------------
__global__ void twinit_kernel() {
    int t = blockIdx.x * blockDim.x + threadIdx.x;
    if (t < NFFT) {
        double s, c;
        sincospi(-(double)t / 8000.0, &s, &c);
        g_tw[t] = make_float2((float)c, (float)s);
    }
}

// ---------------------------------------------------------------------------
// W -> fp16, padded to OUTP rows (pad rows = 0)
// ---------------------------------------------------------------------------
__global__ void wconv_kernel(const float* __restrict__ W) {
    int row = blockIdx.x;
    const float4* src = (const float4*)(W + (size_t)row * NFFT);
    uint2* dst = (uint2*)(g_w16 + (size_t)row * NFFT);
    bool ok = row < OUTN;
    for (int c4 = threadIdx.x; c4 < NFFT / 4; c4 += blockDim.x) {
        float4 v = ok ? __ldg(src + c4) : make_float4(0.f, 0.f, 0.f, 0.f);
        __half2 lo2 = __floats2half2_rn(v.x, v.y);
        __half2 hi2 = __floats2half2_rn(v.z, v.w);
        uint2 p;
        p.x = *(const uint32_t*)&lo2;
        p.y = *(const uint32_t*)&hi2;
        dst[c4] = p;
    }
}

// ---------------------------------------------------------------------------
// Fused count-sketch + forward FFT(p0 + i p1) + pointwise product + inverse
// FFT. Radix-2 stages fused in register pairs; mid twiddles folded into
// adjacent radix-2 sweeps. One block per batch row. Output: z as fp16.
// ---------------------------------------------------------------------------

// forward DIT fused pair: stage len=L then len=2L (butterflies over n2, stride 125)
__device__ __forceinline__ void fwd_r2_pair(float2* sh, int tid, int L) {
    const int H = L >> 1, s1 = NFFT / L, s2 = (NFFT / 2) / L;
    for (int t = tid; t < 4000; t += TPB) {
        int col = t % 125, q = t / 125;
        int g = q / H, p = q - g * H;
        int base = col + 125 * (g * 2 * L + p);
        float2 v0 = sh[base];
        float2 v1 = sh[base + 125 * H];
        float2 v2 = sh[base + 125 * L];
        float2 v3 = sh[base + 125 * (L + H)];
        float2 w1 = __ldg(&g_tw[p * s1]);
        float2 t1 = cmul(w1, v1), t3 = cmul(w1, v3);
        float2 x0 = cadd(v0, t1), x1 = csub(v0, t1);
        float2 x2 = cadd(v2, t3), x3 = csub(v2, t3);
        float2 w2 = __ldg(&g_tw[p * s2]);
        float2 w2b = __ldg(&g_tw[(p + H) * s2]);
        float2 u2 = cmul(w2, x2), u3 = cmul(w2b, x3);
        sh[base]                 = cadd(x0, u2);
        sh[base + 125 * H]       = cadd(x1, u3);
        sh[base + 125 * L]       = csub(x0, u2);
        sh[base + 125 * (L + H)] = csub(x1, u3);
    }
    __syncthreads();
}

// inverse DIF fused pair: stage len=2L then len=L. midfold: multiply inputs
// by conj(tw[n1*k2]) (only for the first pair, 2L = 128).
__device__ __forceinline__ void inv_r2_pair(float2* sh, int tid, int L, bool midfold) {
    const int H = L >> 1, s1 = NFFT / L, s2 = (NFFT / 2) / L;
    for (int t = tid; t < 4000; t += TPB) {
        int col = t % 125, q = t / 125;
        int g = q / H, p = q - g * H;
        int base = col + 125 * (g * 2 * L + p);
        float2 v0 = sh[base];
        float2 v1 = sh[base + 125 * H];
        float2 v2 = sh[base + 125 * L];
        float2 v3 = sh[base + 125 * (L + H)];
        if (midfold) {  // 2L == 128: g == 0, positions p, p+H, p+L, p+L+H
            int n1 = rev5(col);
            v0 = cmulc(v0, __ldg(&g_tw[n1 * p]));
            v1 = cmulc(v1, __ldg(&g_tw[n1 * (p + H)]));
            v2 = cmulc(v2, __ldg(&g_tw[n1 * (p + L)]));
            v3 = cmulc(v3, __ldg(&g_tw[n1 * (p + L + H)]));
        }
        float2 w2a = __ldg(&g_tw[p * s2]);
        float2 w2b = __ldg(&g_tw[(p + H) * s2]);
        float2 y0 = cadd(v0, v2), y2 = cmulc(csub(v0, v2), w2a);
        float2 y1 = cadd(v1, v3), y3 = cmulc(csub(v1, v3), w2b);
        float2 w1 = __ldg(&g_tw[p * s1]);
        sh[base]                 = cadd(y0, y1);
        sh[base + 125 * H]       = cmulc(csub(y0, y1), w1);
        sh[base + 125 * L]       = cadd(y2, y3);
        sh[base + 125 * (L + H)] = cmulc(csub(y2, y3), w1);
    }
    __syncthreads();
}

__global__ void __launch_bounds__(TPB, 1) fftconv_kernel(
    const float* __restrict__ x0, const float* __restrict__ x1,
    const int* __restrict__ h0, const int* __restrict__ h1,
    const int* __restrict__ s0, const int* __restrict__ s1)
{
    extern __shared__ float2 sh[];  // 16000 complex = 128000 B
    const int b = blockIdx.x, tid = threadIdx.x;

    for (int i = tid; i < NFFT; i += TPB) sh[i] = make_float2(0.f, 0.f);
    __syncthreads();

    // scatter count sketches (p0 -> re, p1 -> im), pre-permuted addresses
    for (int i = tid; i < DIN; i += TPB) {
        int bin = h0[i];
        float v = x0[b * DIN + i] * (float)(2 * s0[i] - 1);
        int addr = rev5(bin % 125) + 125 * rev7(bin / 125);
        atomicAdd(&sh[addr].x, v);
        bin = h1[i];
        v = x1[b * DIN + i] * (float)(2 * s1[i] - 1);
        addr = rev5(bin % 125) + 125 * rev7(bin / 125);
        atomicAdd(&sh[addr].y, v);
    }
    __syncthreads();

    // ---- forward radix-2 DIT: fused (2,4), (8,16), (32,64) ----
    fwd_r2_pair(sh, tid, 2);
    fwd_r2_pair(sh, tid, 8);
    fwd_r2_pair(sh, tid, 32);

    // ---- forward single stage len=128 with mid-twiddle fold ----
    for (int t = tid; t < 8000; t += TPB) {
        int col = t % 125, pos = t / 125;
        int ia = col + 125 * pos, ib = ia + 125 * 64;
        float2 w = __ldg(&g_tw[pos * 125]);
        float2 A = sh[ia], B = sh[ib];
        float2 tb = cmul(w, B);
        float2 o0 = cadd(A, tb), o1 = csub(A, tb);
        int n1 = rev5(col);
        sh[ia] = cmul(o0, __ldg(&g_tw[n1 * pos]));
        sh[ib] = cmul(o1, __ldg(&g_tw[n1 * (pos + 64)]));
    }
    __syncthreads();

    const float W5c[5]  = {1.f, 0.30901699f, -0.80901699f, -0.80901699f, 0.30901699f};
    const float W5sF[5] = {0.f, -0.95105652f, -0.58778525f, 0.58778525f, 0.95105652f};
    const float W5sI[5] = {0.f,  0.95105652f,  0.58778525f, -0.58778525f, -0.95105652f};

    // ---- forward radix-5 DIT over n1 (stride 1) ----
    for (int len = 5; len <= 125; len *= 5) {
        int span = len / 5, step = NFFT / len;
        for (int t = tid; t < 3200; t += TPB) {
            int k2 = t & 127, bf = t >> 7;
            int g = bf / span, pos = bf - g * span;
            int base = 125 * k2 + g * len + pos;
            float2 a[5];
#pragma unroll
            for (int q = 0; q < 5; q++) a[q] = sh[base + q * span];
#pragma unroll
            for (int t5 = 1; t5 < 5; t5++) {
                float2 w = __ldg(&g_tw[pos * t5 * step]);
                a[t5] = cmul(a[t5], w);
            }
#pragma unroll
            for (int q = 0; q < 5; q++) {
                float2 o = a[0];
#pragma unroll
                for (int t5 = 1; t5 < 5; t5++) {
                    int r = (q * t5) % 5;
                    o.x += a[t5].x * W5c[r] - a[t5].y * W5sF[r];
                    o.y += a[t5].x * W5sF[r] + a[t5].y * W5c[r];
                }
                sh[base + q * span] = o;
            }
        }
        __syncthreads();
    }

    // ---- pointwise: separate P0/P1, Z = P0*P1, Hermitian fill ----
    for (int k = tid; k <= 8000; k += TPB) {
        int kc = (k == 0) ? 0 : (NFFT - k);
        int sA = (k >> 7) + 125 * (k & 127);
        int sB = (kc >> 7) + 125 * (kc & 127);
        float2 FA = sh[sA], FB = sh[sB];
        float p0r = 0.5f * (FA.x + FB.x), p0i = 0.5f * (FA.y - FB.y);
        float p1r = 0.5f * (FA.y + FB.y), p1i = 0.5f * (FB.x - FA.x);
        float zr = p0r * p1r - p0i * p1i;
        float zi = p0r * p1i + p0i * p1r;
        sh[sA] = make_float2(zr, zi);
        if (sB != sA) sh[sB] = make_float2(zr, -zi);
    }
    __syncthreads();

    // ---- inverse radix-5 DIF over k1 (stride 1) ----
    for (int len = 125; len >= 5; len /= 5) {
        int span = len / 5, step = NFFT / len;
        for (int t = tid; t < 3200; t += TPB) {
            int k2 = t & 127, bf = t >> 7;
            int g = bf / span, pos = bf - g * span;
            int base = 125 * k2 + g * len + pos;
            float2 a[5];
#pragma unroll
            for (int q = 0; q < 5; q++) a[q] = sh[base + q * span];
#pragma unroll
            for (int q = 0; q < 5; q++) {
                float2 o = a[0];
#pragma unroll
                for (int t5 = 1; t5 < 5; t5++) {
                    int r = (q * t5) % 5;
                    o.x += a[t5].x * W5c[r] - a[t5].y * W5sI[r];
                    o.y += a[t5].x * W5sI[r] + a[t5].y * W5c[r];
                }
                float2 w = __ldg(&g_tw[pos * q * step]);
                w.y = -w.y;
                sh[base + q * span] = cmul(o, w);
            }
        }
        __syncthreads();
    }

    // ---- inverse radix-2 DIF: fused (128,64) w/ mid fold, (32,16), (8,4) ----
    inv_r2_pair(sh, tid, 64, true);
    inv_r2_pair(sh, tid, 16, false);
    inv_r2_pair(sh, tid, 4, false);

    // ---- inverse single stage len=2 (twiddle = 1) ----
    for (int t = tid; t < 8000; t += TPB) {
        int col = t % 125, bfi = t / 125;
        int ia = col + 125 * (2 * bfi), ib = ia + 125;
        float2 A = sh[ia], B = sh[ib];
        sh[ia] = cadd(A, B);
        sh[ib] = csub(A, B);
    }
    __syncthreads();

    // ---- store z as fp16, unpermute, scale 1/N ----
    for (int n = tid; n < NFFT; n += TPB) {
        int addr = rev5(n % 125) + 125 * rev7(n / 125);
        float zr = sh[addr].x * (1.f / 16000.f);
        g_z16[b * (size_t)NFFT + n] = __float2half_rn(zr);
    }
}

// ---------------------------------------------------------------------------
// GEMM via mma.sync (HMMA fp16), single pass: out = relu(z16 @ W16^T + b)
// fp32 accumulate. CTA tile 128x192, K-chunk 64, 3-stage cp.async pipeline,
// 12 warps (2m x 6n, warp tile 64x32). Grid 16x8 = 128 CTAs = one wave.
// ---------------------------------------------------------------------------
#define GBM 128
#define GBN 192
#define GBK 64
#define GT  384
#define LDA 144                       // smem row pitch bytes (64 fp16 + 8 pad)
#define A_TILE (GBM * LDA)            // 18432
#define B_TILE (GBN * LDA)            // 27648
#define OFF_B    A_TILE
#define ST_STRIDE (A_TILE + B_TILE)           // 46080
#define GSMEM_TOTAL (3 * ST_STRIDE)           // 138240

__device__ __forceinline__ void load_chunk(
    uint32_t sbase, const char* Az, const char* Bw, int kb, int tid)
{
#pragma unroll
    for (int j = 0; j < 3; j++) {           // A: 128 rows x 8 units (1024)
        int u = tid + j * GT;
        if (u < GBM * 8) {
            int row = u >> 3, c = u & 7;
            size_t g = ((size_t)row * NFFT + kb + c * 8) * 2;
            uint32_t so = sbase + row * LDA + c * 16;
            CP_ASYNC16(so, Az + g);
        }
    }
#pragma unroll
    for (int j = 0; j < 4; j++) {           // B: 192 rows x 8 units (1536)
        int u = tid + j * GT;
        int row = u >> 3, c = u & 7;
        size_t g = ((size_t)row * NFFT + kb + c * 8) * 2;
        uint32_t so = sbase + OFF_B + row * LDA + c * 16;
        CP_ASYNC16(so, Bw + g);
    }
}

__global__ void __launch_bounds__(GT, 1) gemm_mma_kernel(
    const float* __restrict__ bias, float* __restrict__ out)
{
    extern __shared__ char smem[];
    const uint32_t sb = smem_u32(smem);
    const int tid = threadIdx.x, wid = tid >> 5, lid = tid & 31;
    const int warp_m = wid & 1, warp_n = wid >> 1;   // 2 x 6 warps
    const int Nbase = blockIdx.x * GBN, Mbase = blockIdx.y * GBM;

    const char* Az = (const char*)(g_z16 + (size_t)Mbase * NFFT);
    const char* Bw = (const char*)(g_w16 + (size_t)Nbase * NFFT);

    float acc[4][4][4];
#pragma unroll
    for (int i = 0; i < 4; i++)
#pragma unroll
        for (int j = 0; j < 4; j++)
#pragma unroll
            for (int q = 0; q < 4; q++) acc[i][j][q] = 0.f;

    // per-lane ldmatrix address components
    const int a_row = warp_m * 64 + (lid & 7) + ((lid >> 3) & 1) * 8;  // + mi*16
    const int a_col = ((lid >> 4) & 1) * 16;                            // + ks*32
    const int b_row = warp_n * 32 + ((lid >> 4) & 1) * 8 + (lid & 7);   // + ng*16
    const int b_col = ((lid >> 3) & 1) * 16;                            // + ks*32

    load_chunk(sb, Az, Bw, 0, tid);
    CP_COMMIT();
    load_chunk(sb + ST_STRIDE, Az, Bw, GBK, tid);
    CP_COMMIT();

    const int NIT = NFFT / GBK;  // 250
    int st_cur = 0, st_pre = 2;  // stage indices (mod 3)
    for (int it = 0; it < NIT; ++it) {
        if (it + 2 < NIT)
            load_chunk(sb + st_pre * ST_STRIDE, Az, Bw, (it + 2) * GBK, tid);
        CP_COMMIT();              // uniform group count (empty at tail)
        CP_WAIT2();
        __syncthreads();

        const uint32_t ab = sb + st_cur * ST_STRIDE;
#pragma unroll
        for (int ks = 0; ks < 4; ks++) {
            uint32_t ah[4][4], bw[2][4];
#pragma unroll
            for (int mi = 0; mi < 4; mi++) {
                uint32_t ad = ab + (a_row + mi * 16) * LDA + ks * 32 + a_col;
                ldmx4(ah[mi], ad);
            }
#pragma unroll
            for (int ng = 0; ng < 2; ng++) {
                uint32_t bd = ab + OFF_B + (b_row + ng * 16) * LDA + ks * 32 + b_col;
                ldmx4(bw[ng], bd);
            }
#pragma unroll
            for (int mi = 0; mi < 4; mi++)
#pragma unroll
                for (int ng = 0; ng < 2; ng++)
#pragma unroll
                    for (int h = 0; h < 2; h++)
                        mma_fp16(acc[mi][ng * 2 + h], ah[mi], &bw[ng][h * 2]);
        }
        __syncthreads();
        st_cur = (st_cur == 2) ? 0 : st_cur + 1;
        st_pre = (st_pre == 2) ? 0 : st_pre + 1;
    }

    // epilogue: bias + relu, fp32 stores
    const int r = lid >> 2, cq = (lid & 3) * 2;
#pragma unroll
    for (int mi = 0; mi < 4; mi++) {
        int m0 = Mbase + warp_m * 64 + mi * 16 + r;
#pragma unroll
        for (int nt = 0; nt < 4; nt++) {
            int n = Nbase + warp_n * 32 + nt * 8 + cq;
            if (n < OUTN) {
                float b0 = __ldg(bias + n), b1 = __ldg(bias + n + 1);
                float2 v0 = make_float2(fmaxf(acc[mi][nt][0] + b0, 0.f),
                                        fmaxf(acc[mi][nt][1] + b1, 0.f));
                float2 v1 = make_float2(fmaxf(acc[mi][nt][2] + b0, 0.f),
                                        fmaxf(acc[mi][nt][3] + b1, 0.f));
                *(float2*)(out + (size_t)m0 * OUTN + n) = v0;
                *(float2*)(out + (size_t)(m0 + 8) * OUTN + n) = v1;
            }
        }
    }
}

// ---------------------------------------------------------------------------
extern "C" void kernel_launch(void* const* d_in, const int* in_sizes, int n_in,
                              void* d_out, int out_size)
{
    const float* x0 = (const float*)d_in[0];
    const float* x1 = (const float*)d_in[1];
    const int* h0 = (const int*)d_in[2];
    const int* h1 = (const int*)d_in[3];
    const int* s0 = (const int*)d_in[4];
    const int* s1 = (const int*)d_in[5];
    const float* W = (const float*)d_in[6];
    const float* bias = (const float*)d_in[7];
    float* out = (float*)d_out;

    twinit_kernel<<<(NFFT + 255) / 256, 256>>>();
    wconv_kernel<<<OUTP, 256>>>(W);

    cudaFuncSetAttribute(fftconv_kernel,
                         cudaFuncAttributeMaxDynamicSharedMemorySize, NFFT * 8);
    fftconv_kernel<<<BATCH, TPB, NFFT * 8>>>(x0, x1, h0, h1, s0, s1);

    cudaFuncSetAttribute(gemm_mma_kernel,
                         cudaFuncAttributeMaxDynamicSharedMemorySize, GSMEM_TOTAL);
    gemm_mma_kernel<<<dim3(OUTP / GBN, BATCH / GBM), GT, GSMEM_TOTAL>>>(bias, out);
}